// round 11
// baseline (speedup 1.0000x reference)
#include <cuda_runtime.h>
#include <math.h>

#define N 1024
#define C 64
#define BATCH 2
#define NMAT 18   // 9 pairs x 2 batches

typedef unsigned long long ull;

__device__ float g_D[(size_t)NMAT * N * N];      // distances -> adjacency source
__device__ float g_G[(size_t)NMAT * N * N];      // p_g @ p_h^T logit matrices
__device__ float g_S[(size_t)BATCH * N * 3 * N]; // summed attention [b][i][3N]
__device__ float g_f [3 * BATCH * N * C];        // features [a][b][i][c]
__device__ float g_fT[3 * BATCH * C * N];        // features [a][b][c][i]
__device__ float g_pT[3 * BATCH * C * N];        // projected features [a][b][o][i]
__device__ float g_sq[3 * BATCH * N];            // squared norms
__device__ float g_rn[3 * BATCH * N];            // 1/max(norm,1e-12)
__device__ double g_stats[NMAT * 2];             // sum, sumsq per matrix

// ---------- f32x2 helpers ----------
__device__ __forceinline__ ull pk2(float x){
    ull r; asm("mov.b64 %0, {%1, %1};" : "=l"(r) : "f"(x)); return r;
}
__device__ __forceinline__ ull pk2f(float x, float y){
    ull r; asm("mov.b64 %0, {%1, %2};" : "=l"(r) : "f"(x), "f"(y)); return r;
}
__device__ __forceinline__ void ffma2(ull &d, ull a, ull b){
    asm("fma.rn.f32x2 %0, %1, %2, %0;" : "+l"(d) : "l"(a), "l"(b));
}
__device__ __forceinline__ float2 up2(ull v){
    float2 f; asm("mov.b64 {%0, %1}, %2;" : "=f"(f.x), "=f"(f.y) : "l"(v)); return f;
}
__device__ __forceinline__ float fsqrt_ap(float x){
    float r; asm("sqrt.approx.f32 %0, %1;" : "=f"(r) : "f"(x)); return r;
}

// ---------- warp reductions ----------
__device__ __forceinline__ float warpRedSum(float v){
    #pragma unroll
    for(int o=16;o;o>>=1) v += __shfl_xor_sync(0xffffffffu, v, o);
    return v;
}
// order-preserving float<->uint keys (exact for all floats incl. negatives)
__device__ __forceinline__ unsigned fkey(float f){
    unsigned b = __float_as_uint(f);
    return (b & 0x80000000u) ? ~b : (b | 0x80000000u);
}
__device__ __forceinline__ float funkey(unsigned k){
    unsigned b = (k & 0x80000000u) ? (k ^ 0x80000000u) : ~k;
    return __uint_as_float(b);
}
// single-instruction integer warp reductions (sm_80+; f32 redux doesn't exist on sm_103)
__device__ __forceinline__ unsigned reduxAddU(unsigned v){
    unsigned r; asm("redux.sync.add.u32 %0, %1, 0xffffffff;" : "=r"(r) : "r"(v)); return r;
}
__device__ __forceinline__ unsigned reduxMaxU(unsigned v){
    unsigned r; asm("redux.sync.max.u32 %0, %1, 0xffffffff;" : "=r"(r) : "r"(v)); return r;
}
__device__ __forceinline__ unsigned reduxMinU(unsigned v){
    unsigned r; asm("redux.sync.min.u32 %0, %1, 0xffffffff;" : "=r"(r) : "r"(v)); return r;
}
__device__ __forceinline__ float reduxMaxF(float v){ return funkey(reduxMaxU(fkey(v))); }
__device__ __forceinline__ float reduxMinF(float v){ return funkey(reduxMinU(fkey(v))); }

__device__ __forceinline__ float blockRedSum(float v, float* sm){
    int tid=threadIdx.x, lane=tid&31, w=tid>>5;
    v = warpRedSum(v);
    if(lane==0) sm[w]=v;
    __syncthreads();
    if(w==0){
        float x = (lane<8)? sm[lane] : 0.0f;
        x = warpRedSum(x);
        if(lane==0) sm[0]=x;
    }
    __syncthreads();
    float r = sm[0];
    __syncthreads();
    return r;
}

// ---------- front: zero-out + zero-stats + transpose prep ----------
__global__ void k_front(const float* __restrict__ x1, const float* __restrict__ x2,
                        const float* __restrict__ x3, float* __restrict__ out){
    int bx = blockIdx.x;
    if(bx < 1536){
        int ab = bx >> 8; int a = ab>>1, b = ab&1;
        const float* x = (a==0)? x1 : ((a==1)? x2 : x3);
        int idx = (bx & 255)*256 + threadIdx.x;
        int c = idx >> 10, i = idx & 1023;
        float v = x[b*C*N + c*N + i];
        g_fT[(ab*C + c)*N + i] = v;
        g_f [(ab*N + i)*C + c] = v;
    } else if(bx < 1536 + 128){
        int t = (bx - 1536)*256 + threadIdx.x;
        ((float4*)out)[t] = make_float4(0.f,0.f,0.f,0.f);
    } else {
        if(threadIdx.x < NMAT*2) g_stats[threadIdx.x] = 0.0;
    }
}

// ---------- mid: norms + projection ----------
__global__ void k_mid(const float* __restrict__ w1, const float* __restrict__ b1,
                      const float* __restrict__ w2, const float* __restrict__ b2,
                      const float* __restrict__ w3, const float* __restrict__ b3){
    __shared__ float sw[64][65];
    __shared__ float sf[64][65];
    __shared__ float sb[64];
    int bx = blockIdx.x;
    if(bx < 24){
        int t = bx*256 + threadIdx.x;      // 0..6143
        int ab = t >> 10, i = t & 1023;
        const float* p = g_fT + (size_t)ab*C*N + i;
        float s = 0.f;
        #pragma unroll 8
        for(int c = 0; c < 64; ++c){ float v = p[(size_t)c*N]; s += v*v; }
        g_sq[ab*N + i] = s;
        g_rn[ab*N + i] = 1.0f / fmaxf(sqrtf(s), 1e-12f);
        return;
    }
    int pbx = bx - 24;                     // 0..95
    int ab = pbx >> 4; int a = ab>>1;
    const float* W  = (a==0)? w1 : ((a==1)? w2 : w3);
    const float* Bv = (a==0)? b1 : ((a==1)? b2 : b3);
    int tid = threadIdx.x;
    int i0 = (pbx & 15) * 64;
    for(int t = tid; t < 4096; t += 256){
        int r = t>>6, c = t&63;
        sw[r][c] = W[t];
        sf[r][c] = g_f[((size_t)(ab*N) + i0 + r)*C + c];
    }
    if(tid < 64) sb[tid] = Bv[tid];
    __syncthreads();
    int o = tid & 63, iq = tid >> 6;
    #pragma unroll 1
    for(int r = 0; r < 16; ++r){
        int il = iq*16 + r;
        float acc = sb[o];
        #pragma unroll
        for(int c = 0; c < 64; ++c) acc += sf[il][c] * sw[o][c];
        g_pT[((size_t)(ab*C) + o)*N + i0 + il] = acc;
    }
}

// ---------- merged symmetric-aware gemm (dist + logits in one launch) ----------
__global__ void __launch_bounds__(256, 2) k_gemm_all(){
    extern __shared__ float sm[];
    float* sA = sm;              // [64][128] [c][i]
    float* sB = sm + 64*128;     // [64][128] [c][j]
    __shared__ float sred[32];
    const int GU[6] = {0,1,2,0,0,1};
    const int HU[6] = {0,1,2,1,2,2};
    int y = blockIdx.y;
    int kind = (y >= 12) ? 1 : 0;            // 0: dist, 1: logits
    int r0 = y - kind*12;
    int b = r0 & 1, u = r0 >> 1;
    int g = GU[u], h = HU[u];
    bool sym = (u < 3);
    int ti = blockIdx.x >> 3, tj = blockIdx.x & 7;
    if(sym && ti > tj) return;
    int i0 = ti*128, j0 = tj*128;
    bool mir = (!sym) || (ti < tj);
    const float* srcT = kind ? g_pT : g_fT;
    const float4* Ap = (const float4*)(srcT + (size_t)(g*BATCH + b)*C*N);
    const float4* Bp = (const float4*)(srcT + (size_t)(h*BATCH + b)*C*N);
    int tid = threadIdx.x;
    #pragma unroll
    for(int uu = 0; uu < 8; ++uu){
        int idx = tid + uu*256;
        int c = idx >> 5, q = idx & 31;
        ((float4*)(sA + c*128))[q] = Ap[c*256 + (i0>>2) + q];
        ((float4*)(sB + c*128))[q] = Bp[c*256 + (j0>>2) + q];
    }
    __syncthreads();
    int tx = tid & 15, ty = tid >> 4;
    ull acc[4][8];
    #pragma unroll
    for(int rr=0;rr<4;++rr)
        #pragma unroll
        for(int s=0;s<8;++s) acc[rr][s] = 0ull;
    #pragma unroll 8
    for(int c = 0; c < 64; ++c){
        const float* pa = sA + c*128 + ty*8;
        const float* pb = sB + c*128 + tx*8;
        ull a2[4];
        a2[0] = *(const ull*)(pa);
        a2[1] = *(const ull*)(pa+2);
        a2[2] = *(const ull*)(pa+4);
        a2[3] = *(const ull*)(pa+6);
        float4 b0 = *(const float4*)(pb);
        float4 b1 = *(const float4*)(pb+4);
        ull bd[8];
        bd[0]=pk2(b0.x); bd[1]=pk2(b0.y); bd[2]=pk2(b0.z); bd[3]=pk2(b0.w);
        bd[4]=pk2(b1.x); bd[5]=pk2(b1.y); bd[6]=pk2(b1.z); bd[7]=pk2(b1.w);
        #pragma unroll
        for(int rr=0;rr<4;++rr)
            #pragma unroll
            for(int s=0;s<8;++s) ffma2(acc[rr][s], a2[rr], bd[s]);
    }
    int mfwd = (g*3 + h)*2 + b;
    int mmir = (h*3 + g)*2 + b;
    float* dfwd = (kind ? g_G : g_D) + (size_t)mfwd * N * N;
    float* dmir = (kind ? g_G : g_D) + (size_t)mmir * N * N;
    float s1 = 0.f, s2 = 0.f;
    if(kind == 0){
        float qi[8], qj[8];
        int ib = (g*BATCH+b)*N, jb = (h*BATCH+b)*N;
        #pragma unroll
        for(int uu=0;uu<8;++uu){
            qi[uu] = sym ? g_sq[ib + i0 + ty*8 + uu] : g_rn[ib + i0 + ty*8 + uu];
            qj[uu] = sym ? g_sq[jb + j0 + tx*8 + uu] : g_rn[jb + j0 + tx*8 + uu];
        }
        #pragma unroll
        for(int rr=0;rr<4;++rr){
            #pragma unroll
            for(int s=0;s<8;++s){
                float2 t = up2(acc[rr][s]);
                float v0, v1;
                if(sym){
                    v0 = fsqrt_ap(fmaxf(qi[2*rr]   + qj[s] - 2.0f*t.x, 1e-12f));
                    v1 = fsqrt_ap(fmaxf(qi[2*rr+1] + qj[s] - 2.0f*t.y, 1e-12f));
                } else {
                    v0 = 1.0f - t.x*qi[2*rr]  *qj[s];
                    v1 = 1.0f - t.y*qi[2*rr+1]*qj[s];
                }
                s1 += v0 + v1; s2 += v0*v0 + v1*v1;
                acc[rr][s] = pk2f(v0, v1);
            }
        }
    }
    #pragma unroll
    for(int ii=0; ii<8; ++ii){
        int rr = ii>>1, hi = ii&1;
        float o[8];
        #pragma unroll
        for(int s=0;s<8;++s){
            float2 t = up2(acc[rr][s]);
            o[s] = hi ? t.y : t.x;
        }
        float* dr = dfwd + (size_t)(i0 + ty*8 + ii)*N + j0 + tx*8;
        *(float4*)(dr)   = make_float4(o[0],o[1],o[2],o[3]);
        *(float4*)(dr+4) = make_float4(o[4],o[5],o[6],o[7]);
    }
    if(kind == 0){
        float t1 = blockRedSum(s1, sred);
        float t2 = blockRedSum(s2, sred);
        if(tid == 0){
            double wgt = (sym && ti < tj) ? 2.0 : 1.0;
            atomicAdd(&g_stats[mfwd*2+0], (double)t1 * wgt);
            atomicAdd(&g_stats[mfwd*2+1], (double)t2 * wgt);
            if(!sym){
                atomicAdd(&g_stats[mmir*2+0], (double)t1);
                atomicAdd(&g_stats[mmir*2+1], (double)t2);
            }
        }
    }
    if(mir){
        float4* st4 = (float4*)sm;   // [128][16] float4, XOR-swizzled
        #pragma unroll 1
        for(int st = 0; st < 2; ++st){
            __syncthreads();
            if((ty>>3) == st){
                int cb = (ty & 7)*2;
                #pragma unroll
                for(int s = 0; s < 8; ++s){
                    int jj = tx*8 + s;
                    float2 p0 = up2(acc[0][s]), p1 = up2(acc[1][s]);
                    float2 p2 = up2(acc[2][s]), p3 = up2(acc[3][s]);
                    st4[jj*16 + ((cb+0) ^ tx)] = make_float4(p0.x,p0.y,p1.x,p1.y);
                    st4[jj*16 + ((cb+1) ^ tx)] = make_float4(p2.x,p2.y,p3.x,p3.y);
                }
            }
            __syncthreads();
            #pragma unroll
            for(int u2 = 0; u2 < 8; ++u2){
                int idx = tid + u2*256;
                int jj = idx >> 4, c4 = idx & 15;
                float4 val = st4[jj*16 + (c4 ^ ((jj>>3) & 15))];
                *(float4*)&dmir[(size_t)(j0+jj)*N + i0 + st*64 + c4*4] = val;
            }
        }
    }
}

// ---------- fused adjacency + attention (probe + element-stepping) ----------
__global__ void __launch_bounds__(288, 2) k_fa(){
    const float ETA = 1.0f, ALPHA = 0.08f, BETA = 0.01f, INV_TAU = 0.1f, PROB_TH = 0.8f;
    const float QSCALE = 1048576.0f;   // 2^20
    int i = blockIdx.x, b = blockIdx.y;
    int tid = threadIdx.x, w = tid >> 5, lane = tid & 31;
    __shared__ float sAcc9[9][N];      // 36KB: per-warp softmax rows

    int m = w*BATCH + b;
    size_t off = (size_t)m*N*N + (size_t)i*N;
    const float4* Drow = (const float4*)(g_D + off);
    float4 d4[8];
    #pragma unroll
    for(int k=0;k<8;++k) d4[k] = Drow[k*32 + lane];
    float mx = -1e30f, mn = 1e30f;
    #pragma unroll
    for(int k=0;k<8;++k){
        mx = fmaxf(mx, fmaxf(fmaxf(d4[k].x,d4[k].y), fmaxf(d4[k].z,d4[k].w)));
        mn = fminf(mn, fminf(fminf(d4[k].x,d4[k].y), fminf(d4[k].z,d4[k].w)));
    }
    mx = reduxMaxF(mx);
    mn = reduxMinF(mn);
    float4 e4[8];
    float Z = 0.f, num = 0.f;
    #pragma unroll
    for(int k=0;k<8;++k){
        float ex = __expf((mn - d4[k].x)*INV_TAU);
        float ey = __expf((mn - d4[k].y)*INV_TAU);
        float ez = __expf((mn - d4[k].z)*INV_TAU);
        float ew = __expf((mn - d4[k].w)*INV_TAU);
        e4[k] = make_float4(ex,ey,ez,ew);
        Z += ex+ey+ez+ew;
        num += ex*(d4[k].x-mn) + ey*(d4[k].y-mn) + ez*(d4[k].z-mn) + ew*(d4[k].w-mn);
    }
    Z   = warpRedSum(Z);
    num = warpRedSum(num);
    float entropy = logf(Z) + num*INV_TAU/Z;
    float decay = __expf(-ETA*entropy);
    double ssum = g_stats[m*2+0], ssq = g_stats[m*2+1];
    const double N2 = (double)N*(double)N;
    double mu  = ssum / N2;
    double var = (ssq - ssum*ssum/N2) / (N2 - 1.0);
    float sigma = (float)sqrt(fmax(var, 0.0));
    float Tc = (float)mu + ALPHA*sigma;
    unsigned threshi = (unsigned)(PROB_TH * Z * QSCALE);

    // full probe: S~(mid) = redux over floor(lane_sum * 2^20); monotone in mid
    auto fullProbe = [&](float mid)->unsigned{
        float s0=0,s1=0,s2=0,s3=0,s4=0,s5=0,s6=0,s7=0;
        #pragma unroll
        for(int k=0;k<8;k+=2){
            if(d4[k].x   <= mid) s0 += e4[k].x;
            if(d4[k].y   <= mid) s1 += e4[k].y;
            if(d4[k].z   <= mid) s2 += e4[k].z;
            if(d4[k].w   <= mid) s3 += e4[k].w;
            if(d4[k+1].x <= mid) s4 += e4[k+1].x;
            if(d4[k+1].y <= mid) s5 += e4[k+1].y;
            if(d4[k+1].z <= mid) s6 += e4[k+1].z;
            if(d4[k+1].w <= mid) s7 += e4[k+1].w;
        }
        float s = (((s0+s1)+(s2+s3)) + ((s4+s5)+(s6+s7)));
        return reduxAddU(__float2uint_rz(s * QSCALE));
    };

    // phase 1: 8 probes (alternate regula-falsi / midpoint) narrow the bracket
    float flo = 0.0f, fhi = mx;
    unsigned slo = 0u, shi = (unsigned)(Z * QSCALE) + 2048u;
    #pragma unroll 1
    for(int it = 0; it < 8; ++it){
        float mid;
        if(it & 1){
            mid = 0.5f*(flo + fhi);
        } else {
            float frac = (float)(threshi - slo) / fmaxf((float)(shi - slo), 1.0f);
            mid = flo + (fhi - flo)*frac;
            if(!(mid > flo && mid < fhi)) mid = 0.5f*(flo + fhi);
        }
        unsigned si = fullProbe(mid);
        if(si > threshi){ fhi = mid; shi = si; } else { flo = mid; slo = si; }
    }
    // phase 2: element stepping — find d* = smallest element whose inclusion
    // crosses the threshold; selection = {d < d*}. Each step consumes >=1 element.
    float tlo = flo;
    bool done = false;
    #pragma unroll 1
    for(int step = 0; step < 16 && !done; ++step){
        float cmin = 3.4e38f;
        #pragma unroll
        for(int k=0;k<8;++k){
            if(d4[k].x > flo) cmin = fminf(cmin, d4[k].x);
            if(d4[k].y > flo) cmin = fminf(cmin, d4[k].y);
            if(d4[k].z > flo) cmin = fminf(cmin, d4[k].z);
            if(d4[k].w > flo) cmin = fminf(cmin, d4[k].w);
        }
        cmin = reduxMinF(cmin);
        if(cmin > fhi){ tlo = flo; done = true; break; }  // no elements left in bracket
        unsigned si = fullProbe(cmin);
        if(si > threshi){
            tlo = funkey(fkey(cmin) - 1u);   // prevfloat(cmin): selection {d < d*}
            done = true;
        } else {
            flo = cmin; slo = si;
        }
    }
    if(!done){
        // pathological clustering: guarded key-space bisection (bounded, no hang)
        unsigned lo = fkey(flo), hi = fkey(fhi);
        #pragma unroll 1
        for(int guard = 0; guard < 40 && (hi - lo > 1u); ++guard){
            unsigned midb = lo + ((hi - lo) >> 1);
            unsigned si = fullProbe(funkey(midb));
            if(si > threshi) hi = midb; else lo = midb;
        }
        tlo = funkey(lo);
    }
    // merged per-row threshold: d < Tc + BETA*(1-d/dmax)*decay  <=>  d < dT
    float bd = BETA*decay;
    float rdmax = 1.0f / mx;
    float dT = fmaxf((Tc + bd) / (1.0f + bd*rdmax), 1e-30f);
    float dTexcl = __uint_as_float(__float_as_uint(dT) - 1u);  // prevfloat(dT), dT>0
    float cutoff = fminf(tlo, dTexcl);

    const float4* Grow = (const float4*)(g_G + off);
    float4 p4[8];
    float lmax = 0.0f;   // logits are (sel? G : 0); max includes 0
    #pragma unroll
    for(int k=0;k<8;++k){
        float4 gg = Grow[k*32 + lane];
        float4 dd = d4[k];
        float lx = (dd.x <= cutoff) ? gg.x : 0.f;
        float ly = (dd.y <= cutoff) ? gg.y : 0.f;
        float lz = (dd.z <= cutoff) ? gg.z : 0.f;
        float lw = (dd.w <= cutoff) ? gg.w : 0.f;
        p4[k] = make_float4(lx,ly,lz,lw);
        lmax = fmaxf(lmax, fmaxf(fmaxf(lx,ly), fmaxf(lz,lw)));
    }
    lmax = reduxMaxF(lmax);
    float Zs = 0.f;
    #pragma unroll
    for(int k=0;k<8;++k){
        float ex = __expf(p4[k].x - lmax);
        float ey = __expf(p4[k].y - lmax);
        float ez = __expf(p4[k].z - lmax);
        float ew = __expf(p4[k].w - lmax);
        p4[k] = make_float4(ex,ey,ez,ew);
        Zs += ex+ey+ez+ew;
    }
    Zs = warpRedSum(Zs);
    float inv = 1.0f / Zs;
    // each warp writes its own smem slab, then one block reduce to g_S
    float4* slab = (float4*)sAcc9[w];
    #pragma unroll
    for(int k=0;k<8;++k){
        float4 v = p4[k];
        v.x *= inv; v.y *= inv; v.z *= inv; v.w *= inv;
        slab[k*32 + lane] = v;
    }
    __syncthreads();
    float4* Srow = (float4*)(g_S + ((size_t)(b*N + i))*3*N);
    #pragma unroll 1
    for(int t4 = tid; t4 < 768; t4 += 288){
        int hh = t4 >> 8, j4 = t4 & 255;
        float4 a0 = ((const float4*)sAcc9[0*3+hh])[j4];
        float4 a1 = ((const float4*)sAcc9[1*3+hh])[j4];
        float4 a2 = ((const float4*)sAcc9[2*3+hh])[j4];
        Srow[t4] = make_float4(a0.x+a1.x+a2.x, a0.y+a1.y+a2.y,
                               a0.z+a1.z+a2.z, a0.w+a1.w+a2.w);
    }
}

// ---------- final: o[b][c][i] += sum_j S[b][i][hN+j] f[h][b][j][c] ----------
__global__ void k_final3(float* __restrict__ out){
    int b = blockIdx.y, h = blockIdx.z;
    int i0 = blockIdx.x * 16;
    __shared__ float sST[64][18];   // [k][i], row-pairs contiguous for f32x2
    __shared__ float sF[64][65];
    int tid = threadIdx.x;
    int c = tid & 63, iq = tid >> 6;
    ull acc2[2] = {0ull, 0ull};
    #pragma unroll 1
    for(int kk2 = 0; kk2 < 16; ++kk2){
        {
            int r = tid >> 4, kb = (tid & 15)*4;
            const float* sp = g_S + ((size_t)(b*N + i0 + r))*3*N + h*N + kk2*64 + kb;
            float4 v = *(const float4*)sp;
            sST[kb+0][r] = v.x; sST[kb+1][r] = v.y;
            sST[kb+2][r] = v.z; sST[kb+3][r] = v.w;
        }
        {
            int j0 = kk2*64;
            const float* fp = g_f + ((size_t)(h*BATCH + b)*N + j0)*C;
            #pragma unroll
            for(int uu=0; uu<16; ++uu){
                int t = tid + uu*256;
                int r = t >> 6, cc = t & 63;
                sF[r][cc] = fp[r*C + cc];
            }
        }
        __syncthreads();
        #pragma unroll 8
        for(int k = 0; k < 64; ++k){
            ull fvd = pk2(sF[k][c]);
            ull r01 = *(const ull*)&sST[k][iq*4];
            ull r23 = *(const ull*)&sST[k][iq*4+2];
            ffma2(acc2[0], r01, fvd);
            ffma2(acc2[1], r23, fvd);
        }
        __syncthreads();
    }
    float2 a01 = up2(acc2[0]), a23 = up2(acc2[1]);
    float* ob = out + (size_t)b*C*N + (size_t)c*N + i0 + iq*4;
    atomicAdd(ob+0, a01.x);
    atomicAdd(ob+1, a01.y);
    atomicAdd(ob+2, a23.x);
    atomicAdd(ob+3, a23.y);
}

extern "C" void kernel_launch(void* const* d_in, const int* in_sizes, int n_in,
                              void* d_out, int out_size){
    const float* x1 = (const float*)d_in[0];
    const float* x2 = (const float*)d_in[1];
    const float* x3 = (const float*)d_in[2];
    const float* w1 = (const float*)d_in[3];
    const float* b1 = (const float*)d_in[4];
    const float* w2 = (const float*)d_in[5];
    const float* b2 = (const float*)d_in[6];
    const float* w3 = (const float*)d_in[7];
    const float* b3 = (const float*)d_in[8];
    float* out = (float*)d_out;

    static int smem_set = 0;
    if(!smem_set){
        cudaFuncSetAttribute(k_gemm_all, cudaFuncAttributeMaxDynamicSharedMemorySize, 65536);
        smem_set = 1;
    }

    k_front<<<1665, 256>>>(x1, x2, x3, out);
    k_mid<<<120, 256>>>(w1, b1, w2, b2, w3, b3);
    k_gemm_all<<<dim3(64, 24), 256, 65536>>>();
    k_fa<<<dim3(N, BATCH), 288>>>();
    k_final3<<<dim3(64, BATCH, 3), 256>>>(out);
}

// round 12
// speedup vs baseline: 1.0856x; 1.0856x over previous
#include <cuda_runtime.h>
#include <math.h>

#define N 1024
#define C 64
#define BATCH 2
#define NMAT 18   // 9 pairs x 2 batches

typedef unsigned long long ull;

__device__ float g_D[(size_t)NMAT * N * N];      // distances -> adjacency source
__device__ float g_G[(size_t)NMAT * N * N];      // p_g @ p_h^T logit matrices
__device__ float g_S[(size_t)BATCH * N * 3 * N]; // summed attention [b][i][3N]
__device__ float g_f [3 * BATCH * N * C];        // features [a][b][i][c]
__device__ float g_fT[3 * BATCH * C * N];        // features [a][b][c][i]
__device__ float g_pT[3 * BATCH * C * N];        // projected features [a][b][o][i]
__device__ float g_sq[3 * BATCH * N];            // squared norms
__device__ float g_rn[3 * BATCH * N];            // 1/max(norm,1e-12)
__device__ double g_stats[NMAT * 2];             // sum, sumsq per matrix

// ---------- f32x2 helpers ----------
__device__ __forceinline__ ull pk2(float x){
    ull r; asm("mov.b64 %0, {%1, %1};" : "=l"(r) : "f"(x)); return r;
}
__device__ __forceinline__ ull pk2f(float x, float y){
    ull r; asm("mov.b64 %0, {%1, %2};" : "=l"(r) : "f"(x), "f"(y)); return r;
}
__device__ __forceinline__ void ffma2(ull &d, ull a, ull b){
    asm("fma.rn.f32x2 %0, %1, %2, %0;" : "+l"(d) : "l"(a), "l"(b));
}
__device__ __forceinline__ float2 up2(ull v){
    float2 f; asm("mov.b64 {%0, %1}, %2;" : "=f"(f.x), "=f"(f.y) : "l"(v)); return f;
}
__device__ __forceinline__ float fsqrt_ap(float x){
    float r; asm("sqrt.approx.f32 %0, %1;" : "=f"(r) : "f"(x)); return r;
}

// ---------- warp reductions ----------
__device__ __forceinline__ float warpRedSum(float v){
    #pragma unroll
    for(int o=16;o;o>>=1) v += __shfl_xor_sync(0xffffffffu, v, o);
    return v;
}
// order-preserving float<->uint keys (exact for all floats incl. negatives)
__device__ __forceinline__ unsigned fkey(float f){
    unsigned b = __float_as_uint(f);
    return (b & 0x80000000u) ? ~b : (b | 0x80000000u);
}
__device__ __forceinline__ float funkey(unsigned k){
    unsigned b = (k & 0x80000000u) ? (k ^ 0x80000000u) : ~k;
    return __uint_as_float(b);
}
// single-instruction integer warp reductions (sm_80+; f32 redux doesn't exist on sm_103)
__device__ __forceinline__ unsigned reduxAddU(unsigned v){
    unsigned r; asm("redux.sync.add.u32 %0, %1, 0xffffffff;" : "=r"(r) : "r"(v)); return r;
}
__device__ __forceinline__ unsigned reduxMaxU(unsigned v){
    unsigned r; asm("redux.sync.max.u32 %0, %1, 0xffffffff;" : "=r"(r) : "r"(v)); return r;
}
__device__ __forceinline__ unsigned reduxMinU(unsigned v){
    unsigned r; asm("redux.sync.min.u32 %0, %1, 0xffffffff;" : "=r"(r) : "r"(v)); return r;
}
__device__ __forceinline__ float reduxMaxF(float v){ return funkey(reduxMaxU(fkey(v))); }
__device__ __forceinline__ float reduxMinF(float v){ return funkey(reduxMinU(fkey(v))); }

__device__ __forceinline__ float blockRedSum(float v, float* sm){
    int tid=threadIdx.x, lane=tid&31, w=tid>>5;
    v = warpRedSum(v);
    if(lane==0) sm[w]=v;
    __syncthreads();
    if(w==0){
        float x = (lane<8)? sm[lane] : 0.0f;
        x = warpRedSum(x);
        if(lane==0) sm[0]=x;
    }
    __syncthreads();
    float r = sm[0];
    __syncthreads();
    return r;
}

// ---------- front: zero-out + zero-stats + transpose prep ----------
__global__ void k_front(const float* __restrict__ x1, const float* __restrict__ x2,
                        const float* __restrict__ x3, float* __restrict__ out){
    int bx = blockIdx.x;
    if(bx < 1536){
        int ab = bx >> 8; int a = ab>>1, b = ab&1;
        const float* x = (a==0)? x1 : ((a==1)? x2 : x3);
        int idx = (bx & 255)*256 + threadIdx.x;
        int c = idx >> 10, i = idx & 1023;
        float v = x[b*C*N + c*N + i];
        g_fT[(ab*C + c)*N + i] = v;
        g_f [(ab*N + i)*C + c] = v;
    } else if(bx < 1536 + 128){
        int t = (bx - 1536)*256 + threadIdx.x;
        ((float4*)out)[t] = make_float4(0.f,0.f,0.f,0.f);
    } else {
        if(threadIdx.x < NMAT*2) g_stats[threadIdx.x] = 0.0;
    }
}

// ---------- mid: norms + projection ----------
__global__ void k_mid(const float* __restrict__ w1, const float* __restrict__ b1,
                      const float* __restrict__ w2, const float* __restrict__ b2,
                      const float* __restrict__ w3, const float* __restrict__ b3){
    __shared__ float sw[64][65];
    __shared__ float sf[64][65];
    __shared__ float sb[64];
    int bx = blockIdx.x;
    if(bx < 24){
        int t = bx*256 + threadIdx.x;      // 0..6143
        int ab = t >> 10, i = t & 1023;
        const float* p = g_fT + (size_t)ab*C*N + i;
        float s = 0.f;
        #pragma unroll 8
        for(int c = 0; c < 64; ++c){ float v = p[(size_t)c*N]; s += v*v; }
        g_sq[ab*N + i] = s;
        g_rn[ab*N + i] = 1.0f / fmaxf(sqrtf(s), 1e-12f);
        return;
    }
    int pbx = bx - 24;                     // 0..95
    int ab = pbx >> 4; int a = ab>>1;
    const float* W  = (a==0)? w1 : ((a==1)? w2 : w3);
    const float* Bv = (a==0)? b1 : ((a==1)? b2 : b3);
    int tid = threadIdx.x;
    int i0 = (pbx & 15) * 64;
    for(int t = tid; t < 4096; t += 256){
        int r = t>>6, c = t&63;
        sw[r][c] = W[t];
        sf[r][c] = g_f[((size_t)(ab*N) + i0 + r)*C + c];
    }
    if(tid < 64) sb[tid] = Bv[tid];
    __syncthreads();
    int o = tid & 63, iq = tid >> 6;
    #pragma unroll 1
    for(int r = 0; r < 16; ++r){
        int il = iq*16 + r;
        float acc = sb[o];
        #pragma unroll
        for(int c = 0; c < 64; ++c) acc += sf[il][c] * sw[o][c];
        g_pT[((size_t)(ab*C) + o)*N + i0 + il] = acc;
    }
}

// ---------- merged symmetric-aware gemm (dist + logits in one launch) ----------
__global__ void __launch_bounds__(256, 2) k_gemm_all(){
    extern __shared__ float sm[];
    float* sA = sm;              // [64][128] [c][i]
    float* sB = sm + 64*128;     // [64][128] [c][j]
    __shared__ float sred[32];
    const int GU[6] = {0,1,2,0,0,1};
    const int HU[6] = {0,1,2,1,2,2};
    int y = blockIdx.y;
    int kind = (y >= 12) ? 1 : 0;            // 0: dist, 1: logits
    int r0 = y - kind*12;
    int b = r0 & 1, u = r0 >> 1;
    int g = GU[u], h = HU[u];
    bool sym = (u < 3);
    int ti = blockIdx.x >> 3, tj = blockIdx.x & 7;
    if(sym && ti > tj) return;
    int i0 = ti*128, j0 = tj*128;
    bool mir = (!sym) || (ti < tj);
    const float* srcT = kind ? g_pT : g_fT;
    const float4* Ap = (const float4*)(srcT + (size_t)(g*BATCH + b)*C*N);
    const float4* Bp = (const float4*)(srcT + (size_t)(h*BATCH + b)*C*N);
    int tid = threadIdx.x;
    #pragma unroll
    for(int uu = 0; uu < 8; ++uu){
        int idx = tid + uu*256;
        int c = idx >> 5, q = idx & 31;
        ((float4*)(sA + c*128))[q] = Ap[c*256 + (i0>>2) + q];
        ((float4*)(sB + c*128))[q] = Bp[c*256 + (j0>>2) + q];
    }
    __syncthreads();
    int tx = tid & 15, ty = tid >> 4;
    ull acc[4][8];
    #pragma unroll
    for(int rr=0;rr<4;++rr)
        #pragma unroll
        for(int s=0;s<8;++s) acc[rr][s] = 0ull;
    #pragma unroll 8
    for(int c = 0; c < 64; ++c){
        const float* pa = sA + c*128 + ty*8;
        const float* pb = sB + c*128 + tx*8;
        ull a2[4];
        a2[0] = *(const ull*)(pa);
        a2[1] = *(const ull*)(pa+2);
        a2[2] = *(const ull*)(pa+4);
        a2[3] = *(const ull*)(pa+6);
        float4 b0 = *(const float4*)(pb);
        float4 b1 = *(const float4*)(pb+4);
        ull bd[8];
        bd[0]=pk2(b0.x); bd[1]=pk2(b0.y); bd[2]=pk2(b0.z); bd[3]=pk2(b0.w);
        bd[4]=pk2(b1.x); bd[5]=pk2(b1.y); bd[6]=pk2(b1.z); bd[7]=pk2(b1.w);
        #pragma unroll
        for(int rr=0;rr<4;++rr)
            #pragma unroll
            for(int s=0;s<8;++s) ffma2(acc[rr][s], a2[rr], bd[s]);
    }
    int mfwd = (g*3 + h)*2 + b;
    int mmir = (h*3 + g)*2 + b;
    float* dfwd = (kind ? g_G : g_D) + (size_t)mfwd * N * N;
    float* dmir = (kind ? g_G : g_D) + (size_t)mmir * N * N;
    float s1 = 0.f, s2 = 0.f;
    if(kind == 0){
        float qi[8], qj[8];
        int ib = (g*BATCH+b)*N, jb = (h*BATCH+b)*N;
        #pragma unroll
        for(int uu=0;uu<8;++uu){
            qi[uu] = sym ? g_sq[ib + i0 + ty*8 + uu] : g_rn[ib + i0 + ty*8 + uu];
            qj[uu] = sym ? g_sq[jb + j0 + tx*8 + uu] : g_rn[jb + j0 + tx*8 + uu];
        }
        #pragma unroll
        for(int rr=0;rr<4;++rr){
            #pragma unroll
            for(int s=0;s<8;++s){
                float2 t = up2(acc[rr][s]);
                float v0, v1;
                if(sym){
                    v0 = fsqrt_ap(fmaxf(qi[2*rr]   + qj[s] - 2.0f*t.x, 1e-12f));
                    v1 = fsqrt_ap(fmaxf(qi[2*rr+1] + qj[s] - 2.0f*t.y, 1e-12f));
                } else {
                    v0 = 1.0f - t.x*qi[2*rr]  *qj[s];
                    v1 = 1.0f - t.y*qi[2*rr+1]*qj[s];
                }
                s1 += v0 + v1; s2 += v0*v0 + v1*v1;
                acc[rr][s] = pk2f(v0, v1);
            }
        }
    }
    #pragma unroll
    for(int ii=0; ii<8; ++ii){
        int rr = ii>>1, hi = ii&1;
        float o[8];
        #pragma unroll
        for(int s=0;s<8;++s){
            float2 t = up2(acc[rr][s]);
            o[s] = hi ? t.y : t.x;
        }
        float* dr = dfwd + (size_t)(i0 + ty*8 + ii)*N + j0 + tx*8;
        *(float4*)(dr)   = make_float4(o[0],o[1],o[2],o[3]);
        *(float4*)(dr+4) = make_float4(o[4],o[5],o[6],o[7]);
    }
    if(kind == 0){
        float t1 = blockRedSum(s1, sred);
        float t2 = blockRedSum(s2, sred);
        if(tid == 0){
            double wgt = (sym && ti < tj) ? 2.0 : 1.0;
            atomicAdd(&g_stats[mfwd*2+0], (double)t1 * wgt);
            atomicAdd(&g_stats[mfwd*2+1], (double)t2 * wgt);
            if(!sym){
                atomicAdd(&g_stats[mmir*2+0], (double)t1);
                atomicAdd(&g_stats[mmir*2+1], (double)t2);
            }
        }
    }
    if(mir){
        float4* st4 = (float4*)sm;   // [128][16] float4, XOR-swizzled
        #pragma unroll 1
        for(int st = 0; st < 2; ++st){
            __syncthreads();
            if((ty>>3) == st){
                int cb = (ty & 7)*2;
                #pragma unroll
                for(int s = 0; s < 8; ++s){
                    int jj = tx*8 + s;
                    float2 p0 = up2(acc[0][s]), p1 = up2(acc[1][s]);
                    float2 p2 = up2(acc[2][s]), p3 = up2(acc[3][s]);
                    st4[jj*16 + ((cb+0) ^ tx)] = make_float4(p0.x,p0.y,p1.x,p1.y);
                    st4[jj*16 + ((cb+1) ^ tx)] = make_float4(p2.x,p2.y,p3.x,p3.y);
                }
            }
            __syncthreads();
            #pragma unroll
            for(int u2 = 0; u2 < 8; ++u2){
                int idx = tid + u2*256;
                int jj = idx >> 4, c4 = idx & 15;
                float4 val = st4[jj*16 + (c4 ^ ((jj>>3) & 15))];
                *(float4*)&dmir[(size_t)(j0+jj)*N + i0 + st*64 + c4*4] = val;
            }
        }
    }
}

// ---------- fused adjacency + attention (dual-probe rounds + element step) ----------
__global__ void __launch_bounds__(288, 2) k_fa(){
    const float ETA = 1.0f, ALPHA = 0.08f, BETA = 0.01f, INV_TAU = 0.1f, PROB_TH = 0.8f;
    const float QSCALE = 1048576.0f;   // 2^20
    int i = blockIdx.x, b = blockIdx.y;
    int tid = threadIdx.x, w = tid >> 5, lane = tid & 31;
    __shared__ float sAcc9[9][N];      // 36KB: per-warp softmax rows

    int m = w*BATCH + b;
    size_t off = (size_t)m*N*N + (size_t)i*N;
    const float4* Drow = (const float4*)(g_D + off);
    float4 d4[8];
    #pragma unroll
    for(int k=0;k<8;++k) d4[k] = Drow[k*32 + lane];
    float mx = -1e30f, mn = 1e30f;
    #pragma unroll
    for(int k=0;k<8;++k){
        mx = fmaxf(mx, fmaxf(fmaxf(d4[k].x,d4[k].y), fmaxf(d4[k].z,d4[k].w)));
        mn = fminf(mn, fminf(fminf(d4[k].x,d4[k].y), fminf(d4[k].z,d4[k].w)));
    }
    mx = reduxMaxF(mx);
    mn = reduxMinF(mn);
    float4 e4[8];
    float Z = 0.f, num = 0.f;
    #pragma unroll
    for(int k=0;k<8;++k){
        float ex = __expf((mn - d4[k].x)*INV_TAU);
        float ey = __expf((mn - d4[k].y)*INV_TAU);
        float ez = __expf((mn - d4[k].z)*INV_TAU);
        float ew = __expf((mn - d4[k].w)*INV_TAU);
        e4[k] = make_float4(ex,ey,ez,ew);
        Z += ex+ey+ez+ew;
        num += ex*(d4[k].x-mn) + ey*(d4[k].y-mn) + ez*(d4[k].z-mn) + ew*(d4[k].w-mn);
    }
    Z   = warpRedSum(Z);
    num = warpRedSum(num);
    float entropy = logf(Z) + num*INV_TAU/Z;
    float decay = __expf(-ETA*entropy);
    double ssum = g_stats[m*2+0], ssq = g_stats[m*2+1];
    const double N2 = (double)N*(double)N;
    double mu  = ssum / N2;
    double var = (ssq - ssum*ssum/N2) / (N2 - 1.0);
    float sigma = (float)sqrt(fmax(var, 0.0));
    float Tc = (float)mu + ALPHA*sigma;
    unsigned threshi = (unsigned)(PROB_TH * Z * QSCALE);

    // single full probe (quantized, monotone)
    auto fullProbe = [&](float mid)->unsigned{
        float s0=0,s1=0,s2=0,s3=0;
        #pragma unroll
        for(int k=0;k<8;++k){
            if(d4[k].x <= mid) s0 += e4[k].x;
            if(d4[k].y <= mid) s1 += e4[k].y;
            if(d4[k].z <= mid) s2 += e4[k].z;
            if(d4[k].w <= mid) s3 += e4[k].w;
        }
        return reduxAddU(__float2uint_rz(((s0+s1)+(s2+s3)) * QSCALE));
    };

    // phase 1: 7 dual-probe rounds (interp + midpoint fused into one scan).
    // probes at ma=min(mi,mid), mb=max(mi,mid); quantized sums monotone so
    // sa<=sb; bracket update keeps flo<=fhi, slo<=thresh<shi. No inversion.
    float flo = 0.0f, fhi = mx;
    unsigned slo = 0u, shi = (unsigned)(Z * QSCALE) + 2048u;
    #pragma unroll 1
    for(int it = 0; it < 7; ++it){
        float span = fhi - flo;
        float frac = (float)(threshi - slo) / fmaxf((float)(shi - slo), 1.0f);
        float mi  = flo + span*frac;
        float mid = flo + 0.5f*span;
        float ma = fminf(mi, mid), mb = fmaxf(mi, mid);
        float a0=0,a1=0,a2=0,a3=0, b0=0,b1=0,b2=0,b3=0;
        #pragma unroll
        for(int k=0;k<8;++k){
            if(d4[k].x <= ma) a0 += e4[k].x;
            if(d4[k].y <= ma) a1 += e4[k].y;
            if(d4[k].z <= ma) a2 += e4[k].z;
            if(d4[k].w <= ma) a3 += e4[k].w;
            if(d4[k].x <= mb) b0 += e4[k].x;
            if(d4[k].y <= mb) b1 += e4[k].y;
            if(d4[k].z <= mb) b2 += e4[k].z;
            if(d4[k].w <= mb) b3 += e4[k].w;
        }
        unsigned qa = __float2uint_rz(((a0+a1)+(a2+a3)) * QSCALE);
        unsigned qb = __float2uint_rz(((b0+b1)+(b2+b3)) * QSCALE);
        unsigned sa = reduxAddU(qa);
        unsigned sb = reduxAddU(qb);
        if(sa > threshi){ fhi = ma; shi = sa; }
        else if(sb > threshi){ flo = ma; slo = sa; fhi = mb; shi = sb; }
        else { flo = mb; slo = sb; }
    }
    // phase 2: element stepping — d* = smallest element crossing the threshold;
    // selection = {d < d*}. Bracket now holds ~1 element, so ~1 step.
    float tlo = flo;
    bool done = false;
    #pragma unroll 1
    for(int step = 0; step < 10 && !done; ++step){
        float cmin = 3.4e38f;
        #pragma unroll
        for(int k=0;k<8;++k){
            if(d4[k].x > flo) cmin = fminf(cmin, d4[k].x);
            if(d4[k].y > flo) cmin = fminf(cmin, d4[k].y);
            if(d4[k].z > flo) cmin = fminf(cmin, d4[k].z);
            if(d4[k].w > flo) cmin = fminf(cmin, d4[k].w);
        }
        cmin = reduxMinF(cmin);
        if(cmin > fhi){ tlo = flo; done = true; break; }  // nothing left in bracket
        unsigned si = fullProbe(cmin);
        if(si > threshi){
            tlo = funkey(fkey(cmin) - 1u);   // prevfloat(cmin)
            done = true;
        } else {
            flo = cmin; slo = si;
        }
    }
    if(!done){
        // pathological clustering: guarded key-space bisection (bounded)
        unsigned lo = fkey(flo), hi = fkey(fhi);
        #pragma unroll 1
        for(int guard = 0; guard < 40 && (hi - lo > 1u); ++guard){
            unsigned midb = lo + ((hi - lo) >> 1);
            unsigned si = fullProbe(funkey(midb));
            if(si > threshi) hi = midb; else lo = midb;
        }
        tlo = funkey(lo);
    }
    // merged per-row threshold: d < Tc + BETA*(1-d/dmax)*decay  <=>  d < dT
    float bd = BETA*decay;
    float rdmax = 1.0f / mx;
    float dT = fmaxf((Tc + bd) / (1.0f + bd*rdmax), 1e-30f);
    float dTexcl = __uint_as_float(__float_as_uint(dT) - 1u);  // prevfloat(dT), dT>0
    float cutoff = fminf(tlo, dTexcl);

    const float4* Grow = (const float4*)(g_G + off);
    float4 p4[8];
    float lmax = 0.0f;   // logits are (sel? G : 0); max includes 0
    #pragma unroll
    for(int k=0;k<8;++k){
        float4 gg = Grow[k*32 + lane];
        float4 dd = d4[k];
        float lx = (dd.x <= cutoff) ? gg.x : 0.f;
        float ly = (dd.y <= cutoff) ? gg.y : 0.f;
        float lz = (dd.z <= cutoff) ? gg.z : 0.f;
        float lw = (dd.w <= cutoff) ? gg.w : 0.f;
        p4[k] = make_float4(lx,ly,lz,lw);
        lmax = fmaxf(lmax, fmaxf(fmaxf(lx,ly), fmaxf(lz,lw)));
    }
    lmax = reduxMaxF(lmax);
    float Zs = 0.f;
    #pragma unroll
    for(int k=0;k<8;++k){
        float ex = __expf(p4[k].x - lmax);
        float ey = __expf(p4[k].y - lmax);
        float ez = __expf(p4[k].z - lmax);
        float ew = __expf(p4[k].w - lmax);
        p4[k] = make_float4(ex,ey,ez,ew);
        Zs += ex+ey+ez+ew;
    }
    Zs = warpRedSum(Zs);
    float inv = 1.0f / Zs;
    // each warp writes its own smem slab, then one block reduce to g_S
    float4* slab = (float4*)sAcc9[w];
    #pragma unroll
    for(int k=0;k<8;++k){
        float4 v = p4[k];
        v.x *= inv; v.y *= inv; v.z *= inv; v.w *= inv;
        slab[k*32 + lane] = v;
    }
    __syncthreads();
    float4* Srow = (float4*)(g_S + ((size_t)(b*N + i))*3*N);
    #pragma unroll 1
    for(int t4 = tid; t4 < 768; t4 += 288){
        int hh = t4 >> 8, j4 = t4 & 255;
        float4 a0 = ((const float4*)sAcc9[0*3+hh])[j4];
        float4 a1 = ((const float4*)sAcc9[1*3+hh])[j4];
        float4 a2 = ((const float4*)sAcc9[2*3+hh])[j4];
        Srow[t4] = make_float4(a0.x+a1.x+a2.x, a0.y+a1.y+a2.y,
                               a0.z+a1.z+a2.z, a0.w+a1.w+a2.w);
    }
}

// ---------- final: o[b][c][i] += sum_j S[b][i][hN+j] f[h][b][j][c] ----------
__global__ void k_final3(float* __restrict__ out){
    int b = blockIdx.y, h = blockIdx.z;
    int i0 = blockIdx.x * 16;
    __shared__ float sST[64][18];   // [k][i], row-pairs contiguous for f32x2
    __shared__ float sF[64][65];
    int tid = threadIdx.x;
    int c = tid & 63, iq = tid >> 6;
    ull acc2[2] = {0ull, 0ull};
    #pragma unroll 1
    for(int kk2 = 0; kk2 < 16; ++kk2){
        {
            int r = tid >> 4, kb = (tid & 15)*4;
            const float* sp = g_S + ((size_t)(b*N + i0 + r))*3*N + h*N + kk2*64 + kb;
            float4 v = *(const float4*)sp;
            sST[kb+0][r] = v.x; sST[kb+1][r] = v.y;
            sST[kb+2][r] = v.z; sST[kb+3][r] = v.w;
        }
        {
            int j0 = kk2*64;
            const float* fp = g_f + ((size_t)(h*BATCH + b)*N + j0)*C;
            #pragma unroll
            for(int uu=0; uu<16; ++uu){
                int t = tid + uu*256;
                int r = t >> 6, cc = t & 63;
                sF[r][cc] = fp[r*C + cc];
            }
        }
        __syncthreads();
        #pragma unroll 8
        for(int k = 0; k < 64; ++k){
            ull fvd = pk2(sF[k][c]);
            ull r01 = *(const ull*)&sST[k][iq*4];
            ull r23 = *(const ull*)&sST[k][iq*4+2];
            ffma2(acc2[0], r01, fvd);
            ffma2(acc2[1], r23, fvd);
        }
        __syncthreads();
    }
    float2 a01 = up2(acc2[0]), a23 = up2(acc2[1]);
    float* ob = out + (size_t)b*C*N + (size_t)c*N + i0 + iq*4;
    atomicAdd(ob+0, a01.x);
    atomicAdd(ob+1, a01.y);
    atomicAdd(ob+2, a23.x);
    atomicAdd(ob+3, a23.y);
}

extern "C" void kernel_launch(void* const* d_in, const int* in_sizes, int n_in,
                              void* d_out, int out_size){
    const float* x1 = (const float*)d_in[0];
    const float* x2 = (const float*)d_in[1];
    const float* x3 = (const float*)d_in[2];
    const float* w1 = (const float*)d_in[3];
    const float* b1 = (const float*)d_in[4];
    const float* w2 = (const float*)d_in[5];
    const float* b2 = (const float*)d_in[6];
    const float* w3 = (const float*)d_in[7];
    const float* b3 = (const float*)d_in[8];
    float* out = (float*)d_out;

    static int smem_set = 0;
    if(!smem_set){
        cudaFuncSetAttribute(k_gemm_all, cudaFuncAttributeMaxDynamicSharedMemorySize, 65536);
        smem_set = 1;
    }

    k_front<<<1665, 256>>>(x1, x2, x3, out);
    k_mid<<<120, 256>>>(w1, b1, w2, b2, w3, b3);
    k_gemm_all<<<dim3(64, 24), 256, 65536>>>();
    k_fa<<<dim3(N, BATCH), 288>>>();
    k_final3<<<dim3(64, BATCH, 3), 256>>>(out);
}

// round 13
// speedup vs baseline: 1.0954x; 1.0090x over previous
#include <cuda_runtime.h>
#include <math.h>

#define N 1024
#define C 64
#define BATCH 2
#define NMAT 18   // 9 pairs x 2 batches

typedef unsigned long long ull;

__device__ float g_D[(size_t)NMAT * N * N];      // distances -> adjacency source
__device__ float g_G[(size_t)NMAT * N * N];      // p_g @ p_h^T logit matrices
__device__ float g_S[(size_t)BATCH * N * 3 * N]; // summed attention [b][i][3N]
__device__ float g_f [3 * BATCH * N * C];        // features [a][b][i][c]
__device__ float g_fT[3 * BATCH * C * N];        // features [a][b][c][i]
__device__ float g_pT[3 * BATCH * C * N];        // projected features [a][b][o][i]
__device__ float g_sq[3 * BATCH * N];            // squared norms
__device__ float g_rn[3 * BATCH * N];            // 1/max(norm,1e-12)
__device__ double g_stats[NMAT * 2];             // sum, sumsq per matrix

// ---------- f32x2 helpers ----------
__device__ __forceinline__ ull pk2(float x){
    ull r; asm("mov.b64 %0, {%1, %1};" : "=l"(r) : "f"(x)); return r;
}
__device__ __forceinline__ ull pk2f(float x, float y){
    ull r; asm("mov.b64 %0, {%1, %2};" : "=l"(r) : "f"(x), "f"(y)); return r;
}
__device__ __forceinline__ void ffma2(ull &d, ull a, ull b){
    asm("fma.rn.f32x2 %0, %1, %2, %0;" : "+l"(d) : "l"(a), "l"(b));
}
__device__ __forceinline__ float2 up2(ull v){
    float2 f; asm("mov.b64 {%0, %1}, %2;" : "=f"(f.x), "=f"(f.y) : "l"(v)); return f;
}
__device__ __forceinline__ float fsqrt_ap(float x){
    float r; asm("sqrt.approx.f32 %0, %1;" : "=f"(r) : "f"(x)); return r;
}

// ---------- warp reductions ----------
__device__ __forceinline__ float warpRedSum(float v){
    #pragma unroll
    for(int o=16;o;o>>=1) v += __shfl_xor_sync(0xffffffffu, v, o);
    return v;
}
// order-preserving float<->uint keys (exact for all floats incl. negatives)
__device__ __forceinline__ unsigned fkey(float f){
    unsigned b = __float_as_uint(f);
    return (b & 0x80000000u) ? ~b : (b | 0x80000000u);
}
__device__ __forceinline__ float funkey(unsigned k){
    unsigned b = (k & 0x80000000u) ? (k ^ 0x80000000u) : ~k;
    return __uint_as_float(b);
}
// single-instruction integer warp reductions (sm_80+; f32 redux doesn't exist on sm_103)
__device__ __forceinline__ unsigned reduxAddU(unsigned v){
    unsigned r; asm("redux.sync.add.u32 %0, %1, 0xffffffff;" : "=r"(r) : "r"(v)); return r;
}
__device__ __forceinline__ unsigned reduxMaxU(unsigned v){
    unsigned r; asm("redux.sync.max.u32 %0, %1, 0xffffffff;" : "=r"(r) : "r"(v)); return r;
}
__device__ __forceinline__ unsigned reduxMinU(unsigned v){
    unsigned r; asm("redux.sync.min.u32 %0, %1, 0xffffffff;" : "=r"(r) : "r"(v)); return r;
}
__device__ __forceinline__ float reduxMaxF(float v){ return funkey(reduxMaxU(fkey(v))); }
__device__ __forceinline__ float reduxMinF(float v){ return funkey(reduxMinU(fkey(v))); }

__device__ __forceinline__ float blockRedSum(float v, float* sm){
    int tid=threadIdx.x, lane=tid&31, w=tid>>5;
    v = warpRedSum(v);
    if(lane==0) sm[w]=v;
    __syncthreads();
    if(w==0){
        float x = (lane<8)? sm[lane] : 0.0f;
        x = warpRedSum(x);
        if(lane==0) sm[0]=x;
    }
    __syncthreads();
    float r = sm[0];
    __syncthreads();
    return r;
}

// ---------- front: zero-out + zero-stats + transpose prep ----------
__global__ void k_front(const float* __restrict__ x1, const float* __restrict__ x2,
                        const float* __restrict__ x3, float* __restrict__ out){
    int bx = blockIdx.x;
    if(bx < 1536){
        int ab = bx >> 8; int a = ab>>1, b = ab&1;
        const float* x = (a==0)? x1 : ((a==1)? x2 : x3);
        int idx = (bx & 255)*256 + threadIdx.x;
        int c = idx >> 10, i = idx & 1023;
        float v = x[b*C*N + c*N + i];
        g_fT[(ab*C + c)*N + i] = v;
        g_f [(ab*N + i)*C + c] = v;
    } else if(bx < 1536 + 128){
        int t = (bx - 1536)*256 + threadIdx.x;
        ((float4*)out)[t] = make_float4(0.f,0.f,0.f,0.f);
    } else {
        if(threadIdx.x < NMAT*2) g_stats[threadIdx.x] = 0.0;
    }
}

// ---------- mid: norms + projection ----------
__global__ void k_mid(const float* __restrict__ w1, const float* __restrict__ b1,
                      const float* __restrict__ w2, const float* __restrict__ b2,
                      const float* __restrict__ w3, const float* __restrict__ b3){
    __shared__ float sw[64][65];
    __shared__ float sf[64][65];
    __shared__ float sb[64];
    int bx = blockIdx.x;
    if(bx < 24){
        int t = bx*256 + threadIdx.x;      // 0..6143
        int ab = t >> 10, i = t & 1023;
        const float* p = g_fT + (size_t)ab*C*N + i;
        float s = 0.f;
        #pragma unroll 8
        for(int c = 0; c < 64; ++c){ float v = p[(size_t)c*N]; s += v*v; }
        g_sq[ab*N + i] = s;
        g_rn[ab*N + i] = 1.0f / fmaxf(sqrtf(s), 1e-12f);
        return;
    }
    int pbx = bx - 24;                     // 0..95
    int ab = pbx >> 4; int a = ab>>1;
    const float* W  = (a==0)? w1 : ((a==1)? w2 : w3);
    const float* Bv = (a==0)? b1 : ((a==1)? b2 : b3);
    int tid = threadIdx.x;
    int i0 = (pbx & 15) * 64;
    for(int t = tid; t < 4096; t += 256){
        int r = t>>6, c = t&63;
        sw[r][c] = W[t];
        sf[r][c] = g_f[((size_t)(ab*N) + i0 + r)*C + c];
    }
    if(tid < 64) sb[tid] = Bv[tid];
    __syncthreads();
    int o = tid & 63, iq = tid >> 6;
    #pragma unroll 1
    for(int r = 0; r < 16; ++r){
        int il = iq*16 + r;
        float acc = sb[o];
        #pragma unroll
        for(int c = 0; c < 64; ++c) acc += sf[il][c] * sw[o][c];
        g_pT[((size_t)(ab*C) + o)*N + i0 + il] = acc;
    }
}

// ---------- merged symmetric-aware gemm (dist + logits in one launch) ----------
__global__ void __launch_bounds__(256, 2) k_gemm_all(){
    extern __shared__ float sm[];
    float* sA = sm;              // [64][128] [c][i]
    float* sB = sm + 64*128;     // [64][128] [c][j]
    __shared__ float sred[32];
    const int GU[6] = {0,1,2,0,0,1};
    const int HU[6] = {0,1,2,1,2,2};
    int y = blockIdx.y;
    int kind = (y >= 12) ? 1 : 0;            // 0: dist, 1: logits
    int r0 = y - kind*12;
    int b = r0 & 1, u = r0 >> 1;
    int g = GU[u], h = HU[u];
    bool sym = (u < 3);
    int ti = blockIdx.x >> 3, tj = blockIdx.x & 7;
    if(sym && ti > tj) return;
    int i0 = ti*128, j0 = tj*128;
    bool mir = (!sym) || (ti < tj);
    const float* srcT = kind ? g_pT : g_fT;
    const float4* Ap = (const float4*)(srcT + (size_t)(g*BATCH + b)*C*N);
    const float4* Bp = (const float4*)(srcT + (size_t)(h*BATCH + b)*C*N);
    int tid = threadIdx.x;
    #pragma unroll
    for(int uu = 0; uu < 8; ++uu){
        int idx = tid + uu*256;
        int c = idx >> 5, q = idx & 31;
        ((float4*)(sA + c*128))[q] = Ap[c*256 + (i0>>2) + q];
        ((float4*)(sB + c*128))[q] = Bp[c*256 + (j0>>2) + q];
    }
    __syncthreads();
    int tx = tid & 15, ty = tid >> 4;
    ull acc[4][8];
    #pragma unroll
    for(int rr=0;rr<4;++rr)
        #pragma unroll
        for(int s=0;s<8;++s) acc[rr][s] = 0ull;
    #pragma unroll 8
    for(int c = 0; c < 64; ++c){
        const float* pa = sA + c*128 + ty*8;
        const float* pb = sB + c*128 + tx*8;
        ull a2[4];
        a2[0] = *(const ull*)(pa);
        a2[1] = *(const ull*)(pa+2);
        a2[2] = *(const ull*)(pa+4);
        a2[3] = *(const ull*)(pa+6);
        float4 b0 = *(const float4*)(pb);
        float4 b1 = *(const float4*)(pb+4);
        ull bd[8];
        bd[0]=pk2(b0.x); bd[1]=pk2(b0.y); bd[2]=pk2(b0.z); bd[3]=pk2(b0.w);
        bd[4]=pk2(b1.x); bd[5]=pk2(b1.y); bd[6]=pk2(b1.z); bd[7]=pk2(b1.w);
        #pragma unroll
        for(int rr=0;rr<4;++rr)
            #pragma unroll
            for(int s=0;s<8;++s) ffma2(acc[rr][s], a2[rr], bd[s]);
    }
    int mfwd = (g*3 + h)*2 + b;
    int mmir = (h*3 + g)*2 + b;
    float* dfwd = (kind ? g_G : g_D) + (size_t)mfwd * N * N;
    float* dmir = (kind ? g_G : g_D) + (size_t)mmir * N * N;
    float s1 = 0.f, s2 = 0.f;
    if(kind == 0){
        float qi[8], qj[8];
        int ib = (g*BATCH+b)*N, jb = (h*BATCH+b)*N;
        #pragma unroll
        for(int uu=0;uu<8;++uu){
            qi[uu] = sym ? g_sq[ib + i0 + ty*8 + uu] : g_rn[ib + i0 + ty*8 + uu];
            qj[uu] = sym ? g_sq[jb + j0 + tx*8 + uu] : g_rn[jb + j0 + tx*8 + uu];
        }
        #pragma unroll
        for(int rr=0;rr<4;++rr){
            #pragma unroll
            for(int s=0;s<8;++s){
                float2 t = up2(acc[rr][s]);
                float v0, v1;
                if(sym){
                    v0 = fsqrt_ap(fmaxf(qi[2*rr]   + qj[s] - 2.0f*t.x, 1e-12f));
                    v1 = fsqrt_ap(fmaxf(qi[2*rr+1] + qj[s] - 2.0f*t.y, 1e-12f));
                } else {
                    v0 = 1.0f - t.x*qi[2*rr]  *qj[s];
                    v1 = 1.0f - t.y*qi[2*rr+1]*qj[s];
                }
                s1 += v0 + v1; s2 += v0*v0 + v1*v1;
                acc[rr][s] = pk2f(v0, v1);
            }
        }
    }
    #pragma unroll
    for(int ii=0; ii<8; ++ii){
        int rr = ii>>1, hi = ii&1;
        float o[8];
        #pragma unroll
        for(int s=0;s<8;++s){
            float2 t = up2(acc[rr][s]);
            o[s] = hi ? t.y : t.x;
        }
        float* dr = dfwd + (size_t)(i0 + ty*8 + ii)*N + j0 + tx*8;
        *(float4*)(dr)   = make_float4(o[0],o[1],o[2],o[3]);
        *(float4*)(dr+4) = make_float4(o[4],o[5],o[6],o[7]);
    }
    if(kind == 0){
        float t1 = blockRedSum(s1, sred);
        float t2 = blockRedSum(s2, sred);
        if(tid == 0){
            double wgt = (sym && ti < tj) ? 2.0 : 1.0;
            atomicAdd(&g_stats[mfwd*2+0], (double)t1 * wgt);
            atomicAdd(&g_stats[mfwd*2+1], (double)t2 * wgt);
            if(!sym){
                atomicAdd(&g_stats[mmir*2+0], (double)t1);
                atomicAdd(&g_stats[mmir*2+1], (double)t2);
            }
        }
    }
    if(mir){
        float4* st4 = (float4*)sm;   // [128][16] float4, XOR-swizzled
        #pragma unroll 1
        for(int st = 0; st < 2; ++st){
            __syncthreads();
            if((ty>>3) == st){
                int cb = (ty & 7)*2;
                #pragma unroll
                for(int s = 0; s < 8; ++s){
                    int jj = tx*8 + s;
                    float2 p0 = up2(acc[0][s]), p1 = up2(acc[1][s]);
                    float2 p2 = up2(acc[2][s]), p3 = up2(acc[3][s]);
                    st4[jj*16 + ((cb+0) ^ tx)] = make_float4(p0.x,p0.y,p1.x,p1.y);
                    st4[jj*16 + ((cb+1) ^ tx)] = make_float4(p2.x,p2.y,p3.x,p3.y);
                }
            }
            __syncthreads();
            #pragma unroll
            for(int u2 = 0; u2 < 8; ++u2){
                int idx = tid + u2*256;
                int jj = idx >> 4, c4 = idx & 15;
                float4 val = st4[jj*16 + (c4 ^ ((jj>>3) & 15))];
                *(float4*)&dmir[(size_t)(j0+jj)*N + i0 + st*64 + c4*4] = val;
            }
        }
    }
}

// ---------- fused adjacency + attention (e in smem slab, 3 blocks/SM) ----------
__global__ void __launch_bounds__(288, 3) k_fa(){
    const float ETA = 1.0f, ALPHA = 0.08f, BETA = 0.01f, INV_TAU = 0.1f, PROB_TH = 0.8f;
    const float QSCALE = 1048576.0f;   // 2^20
    int i = blockIdx.x, b = blockIdx.y;
    int tid = threadIdx.x, w = tid >> 5, lane = tid & 31;
    __shared__ float sAcc9[9][N];      // 36KB: e-values during bisection, p-values at end

    int m = w*BATCH + b;
    size_t off = (size_t)m*N*N + (size_t)i*N;
    const float4* Drow = (const float4*)(g_D + off);
    float4* slab = (float4*)sAcc9[w];   // this warp's private 4KB
    float4 d4[8];
    #pragma unroll
    for(int k=0;k<8;++k) d4[k] = Drow[k*32 + lane];
    float mx = -1e30f, mn = 1e30f;
    #pragma unroll
    for(int k=0;k<8;++k){
        mx = fmaxf(mx, fmaxf(fmaxf(d4[k].x,d4[k].y), fmaxf(d4[k].z,d4[k].w)));
        mn = fminf(mn, fminf(fminf(d4[k].x,d4[k].y), fminf(d4[k].z,d4[k].w)));
    }
    mx = reduxMaxF(mx);
    mn = reduxMinF(mn);
    float Z = 0.f, num = 0.f;
    #pragma unroll
    for(int k=0;k<8;++k){
        float ex = __expf((mn - d4[k].x)*INV_TAU);
        float ey = __expf((mn - d4[k].y)*INV_TAU);
        float ez = __expf((mn - d4[k].z)*INV_TAU);
        float ew = __expf((mn - d4[k].w)*INV_TAU);
        slab[k*32 + lane] = make_float4(ex,ey,ez,ew);   // e -> smem (warp-private)
        Z += ex+ey+ez+ew;
        num += ex*(d4[k].x-mn) + ey*(d4[k].y-mn) + ez*(d4[k].z-mn) + ew*(d4[k].w-mn);
    }
    Z   = warpRedSum(Z);
    num = warpRedSum(num);
    float entropy = logf(Z) + num*INV_TAU/Z;
    float decay = __expf(-ETA*entropy);
    double ssum = g_stats[m*2+0], ssq = g_stats[m*2+1];
    const double N2 = (double)N*(double)N;
    double mu  = ssum / N2;
    double var = (ssq - ssum*ssum/N2) / (N2 - 1.0);
    float sigma = (float)sqrt(fmax(var, 0.0));
    float Tc = (float)mu + ALPHA*sigma;
    unsigned threshi = (unsigned)(PROB_TH * Z * QSCALE);

    // single full probe (quantized, monotone); e read from slab
    auto fullProbe = [&](float mid)->unsigned{
        float s0=0,s1=0,s2=0,s3=0;
        #pragma unroll
        for(int k=0;k<8;++k){
            float4 e = slab[k*32 + lane];
            if(d4[k].x <= mid) s0 += e.x;
            if(d4[k].y <= mid) s1 += e.y;
            if(d4[k].z <= mid) s2 += e.z;
            if(d4[k].w <= mid) s3 += e.w;
        }
        return reduxAddU(__float2uint_rz(((s0+s1)+(s2+s3)) * QSCALE));
    };

    // phase 1: 7 dual-probe rounds (interp + midpoint fused into one scan)
    float flo = 0.0f, fhi = mx;
    unsigned slo = 0u, shi = (unsigned)(Z * QSCALE) + 2048u;
    #pragma unroll 1
    for(int it = 0; it < 7; ++it){
        float span = fhi - flo;
        float frac = (float)(threshi - slo) / fmaxf((float)(shi - slo), 1.0f);
        float mi  = flo + span*frac;
        float mid = flo + 0.5f*span;
        float ma = fminf(mi, mid), mb = fmaxf(mi, mid);
        float a0=0,a1=0,a2=0,a3=0, b0=0,b1=0,b2=0,b3=0;
        #pragma unroll
        for(int k=0;k<8;++k){
            float4 e = slab[k*32 + lane];
            if(d4[k].x <= ma) a0 += e.x;
            if(d4[k].y <= ma) a1 += e.y;
            if(d4[k].z <= ma) a2 += e.z;
            if(d4[k].w <= ma) a3 += e.w;
            if(d4[k].x <= mb) b0 += e.x;
            if(d4[k].y <= mb) b1 += e.y;
            if(d4[k].z <= mb) b2 += e.z;
            if(d4[k].w <= mb) b3 += e.w;
        }
        unsigned qa = __float2uint_rz(((a0+a1)+(a2+a3)) * QSCALE);
        unsigned qb = __float2uint_rz(((b0+b1)+(b2+b3)) * QSCALE);
        unsigned sa = reduxAddU(qa);
        unsigned sb = reduxAddU(qb);
        if(sa > threshi){ fhi = ma; shi = sa; }
        else if(sb > threshi){ flo = ma; slo = sa; fhi = mb; shi = sb; }
        else { flo = mb; slo = sb; }
    }
    // phase 2: element stepping — d* = smallest element crossing the threshold
    float tlo = flo;
    bool done = false;
    #pragma unroll 1
    for(int step = 0; step < 10 && !done; ++step){
        float cmin = 3.4e38f;
        #pragma unroll
        for(int k=0;k<8;++k){
            if(d4[k].x > flo) cmin = fminf(cmin, d4[k].x);
            if(d4[k].y > flo) cmin = fminf(cmin, d4[k].y);
            if(d4[k].z > flo) cmin = fminf(cmin, d4[k].z);
            if(d4[k].w > flo) cmin = fminf(cmin, d4[k].w);
        }
        cmin = reduxMinF(cmin);
        if(cmin > fhi){ tlo = flo; done = true; break; }
        unsigned si = fullProbe(cmin);
        if(si > threshi){
            tlo = funkey(fkey(cmin) - 1u);   // prevfloat(cmin)
            done = true;
        } else {
            flo = cmin; slo = si;
        }
    }
    if(!done){
        unsigned lo = fkey(flo), hi = fkey(fhi);
        #pragma unroll 1
        for(int guard = 0; guard < 40 && (hi - lo > 1u); ++guard){
            unsigned midb = lo + ((hi - lo) >> 1);
            unsigned si = fullProbe(funkey(midb));
            if(si > threshi) hi = midb; else lo = midb;
        }
        tlo = funkey(lo);
    }
    // merged per-row threshold: d < Tc + BETA*(1-d/dmax)*decay  <=>  d < dT
    float bd = BETA*decay;
    float rdmax = 1.0f / mx;
    float dT = fmaxf((Tc + bd) / (1.0f + bd*rdmax), 1e-30f);
    float dTexcl = __uint_as_float(__float_as_uint(dT) - 1u);  // prevfloat(dT), dT>0
    float cutoff = fminf(tlo, dTexcl);

    const float4* Grow = (const float4*)(g_G + off);
    float4 p4[8];
    float lmax = 0.0f;   // logits are (sel? G : 0); max includes 0
    #pragma unroll
    for(int k=0;k<8;++k){
        float4 gg = Grow[k*32 + lane];
        float4 dd = d4[k];
        float lx = (dd.x <= cutoff) ? gg.x : 0.f;
        float ly = (dd.y <= cutoff) ? gg.y : 0.f;
        float lz = (dd.z <= cutoff) ? gg.z : 0.f;
        float lw = (dd.w <= cutoff) ? gg.w : 0.f;
        p4[k] = make_float4(lx,ly,lz,lw);
        lmax = fmaxf(lmax, fmaxf(fmaxf(lx,ly), fmaxf(lz,lw)));
    }
    lmax = reduxMaxF(lmax);
    float Zs = 0.f;
    #pragma unroll
    for(int k=0;k<8;++k){
        float ex = __expf(p4[k].x - lmax);
        float ey = __expf(p4[k].y - lmax);
        float ez = __expf(p4[k].z - lmax);
        float ew = __expf(p4[k].w - lmax);
        p4[k] = make_float4(ex,ey,ez,ew);
        Zs += ex+ey+ez+ew;
    }
    Zs = warpRedSum(Zs);
    float inv = 1.0f / Zs;
    // overwrite slab with normalized probs, then one block reduce to g_S
    #pragma unroll
    for(int k=0;k<8;++k){
        float4 v = p4[k];
        v.x *= inv; v.y *= inv; v.z *= inv; v.w *= inv;
        slab[k*32 + lane] = v;
    }
    __syncthreads();
    float4* Srow = (float4*)(g_S + ((size_t)(b*N + i))*3*N);
    #pragma unroll 1
    for(int t4 = tid; t4 < 768; t4 += 288){
        int hh = t4 >> 8, j4 = t4 & 255;
        float4 a0 = ((const float4*)sAcc9[0*3+hh])[j4];
        float4 a1 = ((const float4*)sAcc9[1*3+hh])[j4];
        float4 a2 = ((const float4*)sAcc9[2*3+hh])[j4];
        Srow[t4] = make_float4(a0.x+a1.x+a2.x, a0.y+a1.y+a2.y,
                               a0.z+a1.z+a2.z, a0.w+a1.w+a2.w);
    }
}

// ---------- final: o[b][c][i] += sum_j S[b][i][hN+j] f[h][b][j][c] ----------
__global__ void k_final3(float* __restrict__ out){
    int b = blockIdx.y, h = blockIdx.z;
    int i0 = blockIdx.x * 16;
    __shared__ float sST[64][18];   // [k][i], row-pairs contiguous for f32x2
    __shared__ float sF[64][65];
    int tid = threadIdx.x;
    int c = tid & 63, iq = tid >> 6;
    ull acc2[2] = {0ull, 0ull};
    #pragma unroll 1
    for(int kk2 = 0; kk2 < 16; ++kk2){
        {
            int r = tid >> 4, kb = (tid & 15)*4;
            const float* sp = g_S + ((size_t)(b*N + i0 + r))*3*N + h*N + kk2*64 + kb;
            float4 v = *(const float4*)sp;
            sST[kb+0][r] = v.x; sST[kb+1][r] = v.y;
            sST[kb+2][r] = v.z; sST[kb+3][r] = v.w;
        }
        {
            int j0 = kk2*64;
            const float* fp = g_f + ((size_t)(h*BATCH + b)*N + j0)*C;
            #pragma unroll
            for(int uu=0; uu<16; ++uu){
                int t = tid + uu*256;
                int r = t >> 6, cc = t & 63;
                sF[r][cc] = fp[r*C + cc];
            }
        }
        __syncthreads();
        #pragma unroll 8
        for(int k = 0; k < 64; ++k){
            ull fvd = pk2(sF[k][c]);
            ull r01 = *(const ull*)&sST[k][iq*4];
            ull r23 = *(const ull*)&sST[k][iq*4+2];
            ffma2(acc2[0], r01, fvd);
            ffma2(acc2[1], r23, fvd);
        }
        __syncthreads();
    }
    float2 a01 = up2(acc2[0]), a23 = up2(acc2[1]);
    float* ob = out + (size_t)b*C*N + (size_t)c*N + i0 + iq*4;
    atomicAdd(ob+0, a01.x);
    atomicAdd(ob+1, a01.y);
    atomicAdd(ob+2, a23.x);
    atomicAdd(ob+3, a23.y);
}

extern "C" void kernel_launch(void* const* d_in, const int* in_sizes, int n_in,
                              void* d_out, int out_size){
    const float* x1 = (const float*)d_in[0];
    const float* x2 = (const float*)d_in[1];
    const float* x3 = (const float*)d_in[2];
    const float* w1 = (const float*)d_in[3];
    const float* b1 = (const float*)d_in[4];
    const float* w2 = (const float*)d_in[5];
    const float* b2 = (const float*)d_in[6];
    const float* w3 = (const float*)d_in[7];
    const float* b3 = (const float*)d_in[8];
    float* out = (float*)d_out;

    static int smem_set = 0;
    if(!smem_set){
        cudaFuncSetAttribute(k_gemm_all, cudaFuncAttributeMaxDynamicSharedMemorySize, 65536);
        smem_set = 1;
    }

    k_front<<<1665, 256>>>(x1, x2, x3, out);
    k_mid<<<120, 256>>>(w1, b1, w2, b2, w3, b3);
    k_gemm_all<<<dim3(64, 24), 256, 65536>>>();
    k_fa<<<dim3(N, BATCH), 288>>>();
    k_final3<<<dim3(64, BATCH, 3), 256>>>(out);
}

// round 15
// speedup vs baseline: 1.1034x; 1.0074x over previous
#include <cuda_runtime.h>
#include <math.h>

#define N 1024
#define C 64
#define BATCH 2
#define NMAT 18   // 9 pairs x 2 batches

typedef unsigned long long ull;

__device__ float g_D[(size_t)NMAT * N * N];      // distances -> adjacency source
__device__ float g_G[(size_t)NMAT * N * N];      // p_g @ p_h^T logit matrices
__device__ float g_S[(size_t)BATCH * N * 3 * N]; // summed attention [b][i][3N]
__device__ float g_f [3 * BATCH * N * C];        // features [a][b][i][c]
__device__ float g_fT[3 * BATCH * C * N];        // features [a][b][c][i]
__device__ float g_pT[3 * BATCH * C * N];        // projected features [a][b][o][i]
__device__ float g_sq[3 * BATCH * N];            // squared norms
__device__ float g_rn[3 * BATCH * N];            // 1/max(norm,1e-12)
__device__ double g_stats[NMAT * 2];             // sum, sumsq per matrix

// ---------- f32x2 helpers ----------
__device__ __forceinline__ ull pk2(float x){
    ull r; asm("mov.b64 %0, {%1, %1};" : "=l"(r) : "f"(x)); return r;
}
__device__ __forceinline__ ull pk2f(float x, float y){
    ull r; asm("mov.b64 %0, {%1, %2};" : "=l"(r) : "f"(x), "f"(y)); return r;
}
__device__ __forceinline__ void ffma2(ull &d, ull a, ull b){
    asm("fma.rn.f32x2 %0, %1, %2, %0;" : "+l"(d) : "l"(a), "l"(b));
}
__device__ __forceinline__ float2 up2(ull v){
    float2 f; asm("mov.b64 {%0, %1}, %2;" : "=f"(f.x), "=f"(f.y) : "l"(v)); return f;
}
__device__ __forceinline__ float fsqrt_ap(float x){
    float r; asm("sqrt.approx.f32 %0, %1;" : "=f"(r) : "f"(x)); return r;
}

// ---------- warp reductions ----------
__device__ __forceinline__ float warpRedSum(float v){
    #pragma unroll
    for(int o=16;o;o>>=1) v += __shfl_xor_sync(0xffffffffu, v, o);
    return v;
}
// order-preserving float<->uint keys (exact for all floats incl. negatives)
__device__ __forceinline__ unsigned fkey(float f){
    unsigned b = __float_as_uint(f);
    return (b & 0x80000000u) ? ~b : (b | 0x80000000u);
}
__device__ __forceinline__ float funkey(unsigned k){
    unsigned b = (k & 0x80000000u) ? (k ^ 0x80000000u) : ~k;
    return __uint_as_float(b);
}
// single-instruction integer warp reductions (sm_80+; f32 redux doesn't exist on sm_103)
__device__ __forceinline__ unsigned reduxAddU(unsigned v){
    unsigned r; asm("redux.sync.add.u32 %0, %1, 0xffffffff;" : "=r"(r) : "r"(v)); return r;
}
__device__ __forceinline__ unsigned reduxMaxU(unsigned v){
    unsigned r; asm("redux.sync.max.u32 %0, %1, 0xffffffff;" : "=r"(r) : "r"(v)); return r;
}
__device__ __forceinline__ unsigned reduxMinU(unsigned v){
    unsigned r; asm("redux.sync.min.u32 %0, %1, 0xffffffff;" : "=r"(r) : "r"(v)); return r;
}
__device__ __forceinline__ float reduxMaxF(float v){ return funkey(reduxMaxU(fkey(v))); }
__device__ __forceinline__ float reduxMinF(float v){ return funkey(reduxMinU(fkey(v))); }

__device__ __forceinline__ float blockRedSum(float v, float* sm){
    int tid=threadIdx.x, lane=tid&31, w=tid>>5;
    v = warpRedSum(v);
    if(lane==0) sm[w]=v;
    __syncthreads();
    if(w==0){
        float x = (lane<8)? sm[lane] : 0.0f;
        x = warpRedSum(x);
        if(lane==0) sm[0]=x;
    }
    __syncthreads();
    float r = sm[0];
    __syncthreads();
    return r;
}

// ---------- front: tiled transpose prep + zero-out + zero-stats ----------
// bx in [0,96): 64x64 tile transpose; [96,224): zero out; 224: zero stats.
__global__ void k_front(const float* __restrict__ x1, const float* __restrict__ x2,
                        const float* __restrict__ x3, float* __restrict__ out){
    __shared__ float sm[64][65];
    int bx = blockIdx.x, tid = threadIdx.x;
    if(bx < 96){
        int ab = bx >> 4; int a = ab>>1, b = ab&1;
        int i0 = (bx & 15) * 64;
        const float4* x4 = (const float4*)((a==0)? x1 : ((a==1)? x2 : x3));
        float4* fT4 = (float4*)g_fT;
        float4* f4  = (float4*)g_f;
        int q = tid & 15, r = tid >> 4;
        #pragma unroll
        for(int u = 0; u < 4; ++u){
            int c = u*16 + r;
            float4 v = x4[(b*C + c)*256 + (i0>>2) + q];
            fT4[(ab*C + c)*256 + (i0>>2) + q] = v;
            sm[c][q*4+0] = v.x;
            sm[c][q*4+1] = v.y;
            sm[c][q*4+2] = v.z;
            sm[c][q*4+3] = v.w;
        }
        __syncthreads();
        int c4 = q * 4;
        #pragma unroll
        for(int u = 0; u < 4; ++u){
            int il = u*16 + r;
            float4 o = make_float4(sm[c4][il], sm[c4+1][il], sm[c4+2][il], sm[c4+3][il]);
            f4[((size_t)(ab*N) + i0 + il)*16 + q] = o;
        }
    } else if(bx < 224){
        int t = (bx - 96)*256 + tid;
        ((float4*)out)[t] = make_float4(0.f,0.f,0.f,0.f);
    } else {
        if(tid < NMAT*2) g_stats[tid] = 0.0;
    }
}

// ---------- mid: norms + projection ----------
__global__ void k_mid(const float* __restrict__ w1, const float* __restrict__ b1,
                      const float* __restrict__ w2, const float* __restrict__ b2,
                      const float* __restrict__ w3, const float* __restrict__ b3){
    __shared__ float sw[64][65];
    __shared__ float sf[64][65];
    __shared__ float sb[64];
    int bx = blockIdx.x;
    if(bx < 24){
        int t = bx*256 + threadIdx.x;      // 0..6143
        int ab = t >> 10, i = t & 1023;
        const float* p = g_fT + (size_t)ab*C*N + i;
        float s = 0.f;
        #pragma unroll 8
        for(int c = 0; c < 64; ++c){ float v = p[(size_t)c*N]; s += v*v; }
        g_sq[ab*N + i] = s;
        g_rn[ab*N + i] = 1.0f / fmaxf(sqrtf(s), 1e-12f);
        return;
    }
    int pbx = bx - 24;                     // 0..95
    int ab = pbx >> 4; int a = ab>>1;
    const float* W  = (a==0)? w1 : ((a==1)? w2 : w3);
    const float* Bv = (a==0)? b1 : ((a==1)? b2 : b3);
    int tid = threadIdx.x;
    int i0 = (pbx & 15) * 64;
    for(int t = tid; t < 4096; t += 256){
        int r = t>>6, c = t&63;
        sw[r][c] = W[t];
        sf[r][c] = g_f[((size_t)(ab*N) + i0 + r)*C + c];
    }
    if(tid < 64) sb[tid] = Bv[tid];
    __syncthreads();
    int o = tid & 63, iq = tid >> 6;
    #pragma unroll 1
    for(int r = 0; r < 16; ++r){
        int il = iq*16 + r;
        float acc = sb[o];
        #pragma unroll
        for(int c = 0; c < 64; ++c) acc += sf[il][c] * sw[o][c];
        g_pT[((size_t)(ab*C) + o)*N + i0 + il] = acc;
    }
}

// ---------- merged symmetric-aware gemm (dist + logits in one launch) ----------
__global__ void __launch_bounds__(256, 2) k_gemm_all(){
    extern __shared__ float sm[];
    float* sA = sm;              // [64][128] [c][i]
    float* sB = sm + 64*128;     // [64][128] [c][j]
    __shared__ float sred[32];
    const int GU[6] = {0,1,2,0,0,1};
    const int HU[6] = {0,1,2,1,2,2};
    int y = blockIdx.y;
    int kind = (y >= 12) ? 1 : 0;            // 0: dist, 1: logits
    int r0 = y - kind*12;
    int b = r0 & 1, u = r0 >> 1;
    int g = GU[u], h = HU[u];
    bool sym = (u < 3);
    int ti = blockIdx.x >> 3, tj = blockIdx.x & 7;
    if(sym && ti > tj) return;
    int i0 = ti*128, j0 = tj*128;
    bool mir = (!sym) || (ti < tj);
    const float* srcT = kind ? g_pT : g_fT;
    const float4* Ap = (const float4*)(srcT + (size_t)(g*BATCH + b)*C*N);
    const float4* Bp = (const float4*)(srcT + (size_t)(h*BATCH + b)*C*N);
    int tid = threadIdx.x;
    #pragma unroll
    for(int uu = 0; uu < 8; ++uu){
        int idx = tid + uu*256;
        int c = idx >> 5, q = idx & 31;
        ((float4*)(sA + c*128))[q] = Ap[c*256 + (i0>>2) + q];
        ((float4*)(sB + c*128))[q] = Bp[c*256 + (j0>>2) + q];
    }
    __syncthreads();
    int tx = tid & 15, ty = tid >> 4;
    ull acc[4][8];
    #pragma unroll
    for(int rr=0;rr<4;++rr)
        #pragma unroll
        for(int s=0;s<8;++s) acc[rr][s] = 0ull;
    #pragma unroll 8
    for(int c = 0; c < 64; ++c){
        const float* pa = sA + c*128 + ty*8;
        const float* pb = sB + c*128 + tx*8;
        ull a2[4];
        a2[0] = *(const ull*)(pa);
        a2[1] = *(const ull*)(pa+2);
        a2[2] = *(const ull*)(pa+4);
        a2[3] = *(const ull*)(pa+6);
        float4 b0 = *(const float4*)(pb);
        float4 b1 = *(const float4*)(pb+4);
        ull bd[8];
        bd[0]=pk2(b0.x); bd[1]=pk2(b0.y); bd[2]=pk2(b0.z); bd[3]=pk2(b0.w);
        bd[4]=pk2(b1.x); bd[5]=pk2(b1.y); bd[6]=pk2(b1.z); bd[7]=pk2(b1.w);
        #pragma unroll
        for(int rr=0;rr<4;++rr)
            #pragma unroll
            for(int s=0;s<8;++s) ffma2(acc[rr][s], a2[rr], bd[s]);
    }
    int mfwd = (g*3 + h)*2 + b;
    int mmir = (h*3 + g)*2 + b;
    float* dfwd = (kind ? g_G : g_D) + (size_t)mfwd * N * N;
    float* dmir = (kind ? g_G : g_D) + (size_t)mmir * N * N;
    float s1 = 0.f, s2 = 0.f;
    if(kind == 0){
        float qi[8], qj[8];
        int ib = (g*BATCH+b)*N, jb = (h*BATCH+b)*N;
        #pragma unroll
        for(int uu=0;uu<8;++uu){
            qi[uu] = sym ? g_sq[ib + i0 + ty*8 + uu] : g_rn[ib + i0 + ty*8 + uu];
            qj[uu] = sym ? g_sq[jb + j0 + tx*8 + uu] : g_rn[jb + j0 + tx*8 + uu];
        }
        #pragma unroll
        for(int rr=0;rr<4;++rr){
            #pragma unroll
            for(int s=0;s<8;++s){
                float2 t = up2(acc[rr][s]);
                float v0, v1;
                if(sym){
                    v0 = fsqrt_ap(fmaxf(qi[2*rr]   + qj[s] - 2.0f*t.x, 1e-12f));
                    v1 = fsqrt_ap(fmaxf(qi[2*rr+1] + qj[s] - 2.0f*t.y, 1e-12f));
                } else {
                    v0 = 1.0f - t.x*qi[2*rr]  *qj[s];
                    v1 = 1.0f - t.y*qi[2*rr+1]*qj[s];
                }
                s1 += v0 + v1; s2 += v0*v0 + v1*v1;
                acc[rr][s] = pk2f(v0, v1);
            }
        }
    }
    #pragma unroll
    for(int ii=0; ii<8; ++ii){
        int rr = ii>>1, hi = ii&1;
        float o[8];
        #pragma unroll
        for(int s=0;s<8;++s){
            float2 t = up2(acc[rr][s]);
            o[s] = hi ? t.y : t.x;
        }
        float* dr = dfwd + (size_t)(i0 + ty*8 + ii)*N + j0 + tx*8;
        *(float4*)(dr)   = make_float4(o[0],o[1],o[2],o[3]);
        *(float4*)(dr+4) = make_float4(o[4],o[5],o[6],o[7]);
    }
    if(kind == 0){
        float t1 = blockRedSum(s1, sred);
        float t2 = blockRedSum(s2, sred);
        if(tid == 0){
            double wgt = (sym && ti < tj) ? 2.0 : 1.0;
            atomicAdd(&g_stats[mfwd*2+0], (double)t1 * wgt);
            atomicAdd(&g_stats[mfwd*2+1], (double)t2 * wgt);
            if(!sym){
                atomicAdd(&g_stats[mmir*2+0], (double)t1);
                atomicAdd(&g_stats[mmir*2+1], (double)t2);
            }
        }
    }
    if(mir){
        float4* st4 = (float4*)sm;   // [128][16] float4, XOR-swizzled
        #pragma unroll 1
        for(int st = 0; st < 2; ++st){
            __syncthreads();
            if((ty>>3) == st){
                int cb = (ty & 7)*2;
                #pragma unroll
                for(int s = 0; s < 8; ++s){
                    int jj = tx*8 + s;
                    float2 p0 = up2(acc[0][s]), p1 = up2(acc[1][s]);
                    float2 p2 = up2(acc[2][s]), p3 = up2(acc[3][s]);
                    st4[jj*16 + ((cb+0) ^ tx)] = make_float4(p0.x,p0.y,p1.x,p1.y);
                    st4[jj*16 + ((cb+1) ^ tx)] = make_float4(p2.x,p2.y,p3.x,p3.y);
                }
            }
            __syncthreads();
            #pragma unroll
            for(int u2 = 0; u2 < 8; ++u2){
                int idx = tid + u2*256;
                int jj = idx >> 4, c4 = idx & 15;
                float4 val = st4[jj*16 + (c4 ^ ((jj>>3) & 15))];
                *(float4*)&dmir[(size_t)(j0+jj)*N + i0 + st*64 + c4*4] = val;
            }
        }
    }
}

// ---------- fused adjacency + attention (e in smem slab, 3 blocks/SM) ----------
__global__ void __launch_bounds__(288, 3) k_fa(){
    const float ETA = 1.0f, ALPHA = 0.08f, BETA = 0.01f, INV_TAU = 0.1f, PROB_TH = 0.8f;
    const float QSCALE = 1048576.0f;   // 2^20
    int i = blockIdx.x, b = blockIdx.y;
    int tid = threadIdx.x, w = tid >> 5, lane = tid & 31;
    __shared__ float sAcc9[9][N];      // 36KB: e-values during bisection, p-values at end

    int m = w*BATCH + b;
    size_t off = (size_t)m*N*N + (size_t)i*N;
    const float4* Drow = (const float4*)(g_D + off);
    float4* slab = (float4*)sAcc9[w];   // this warp's private 4KB
    float4 d4[8];
    #pragma unroll
    for(int k=0;k<8;++k) d4[k] = Drow[k*32 + lane];
    float mx = -1e30f, mn = 1e30f;
    #pragma unroll
    for(int k=0;k<8;++k){
        mx = fmaxf(mx, fmaxf(fmaxf(d4[k].x,d4[k].y), fmaxf(d4[k].z,d4[k].w)));
        mn = fminf(mn, fminf(fminf(d4[k].x,d4[k].y), fminf(d4[k].z,d4[k].w)));
    }
    mx = reduxMaxF(mx);
    mn = reduxMinF(mn);
    float Z = 0.f, num = 0.f;
    #pragma unroll
    for(int k=0;k<8;++k){
        float ex = __expf((mn - d4[k].x)*INV_TAU);
        float ey = __expf((mn - d4[k].y)*INV_TAU);
        float ez = __expf((mn - d4[k].z)*INV_TAU);
        float ew = __expf((mn - d4[k].w)*INV_TAU);
        slab[k*32 + lane] = make_float4(ex,ey,ez,ew);   // e -> smem (warp-private)
        Z += ex+ey+ez+ew;
        num += ex*(d4[k].x-mn) + ey*(d4[k].y-mn) + ez*(d4[k].z-mn) + ew*(d4[k].w-mn);
    }
    Z   = warpRedSum(Z);
    num = warpRedSum(num);
    float entropy = logf(Z) + num*INV_TAU/Z;
    float decay = __expf(-ETA*entropy);
    double ssum = g_stats[m*2+0], ssq = g_stats[m*2+1];
    const double N2 = (double)N*(double)N;
    double mu  = ssum / N2;
    double var = (ssq - ssum*ssum/N2) / (N2 - 1.0);
    float sigma = (float)sqrt(fmax(var, 0.0));
    float Tc = (float)mu + ALPHA*sigma;
    unsigned threshi = (unsigned)(PROB_TH * Z * QSCALE);

    // single full probe (quantized, monotone); e read from slab
    auto fullProbe = [&](float mid)->unsigned{
        float s0=0,s1=0,s2=0,s3=0;
        #pragma unroll
        for(int k=0;k<8;++k){
            float4 e = slab[k*32 + lane];
            if(d4[k].x <= mid) s0 += e.x;
            if(d4[k].y <= mid) s1 += e.y;
            if(d4[k].z <= mid) s2 += e.z;
            if(d4[k].w <= mid) s3 += e.w;
        }
        return reduxAddU(__float2uint_rz(((s0+s1)+(s2+s3)) * QSCALE));
    };

    // phase 1: 7 dual-probe rounds (interp + midpoint fused into one scan)
    float flo = 0.0f, fhi = mx;
    unsigned slo = 0u, shi = (unsigned)(Z * QSCALE) + 2048u;
    #pragma unroll 1
    for(int it = 0; it < 7; ++it){
        float span = fhi - flo;
        float frac = (float)(threshi - slo) / fmaxf((float)(shi - slo), 1.0f);
        float mi  = flo + span*frac;
        float mid = flo + 0.5f*span;
        float ma = fminf(mi, mid), mb = fmaxf(mi, mid);
        float a0=0,a1=0,a2=0,a3=0, b0=0,b1=0,b2=0,b3=0;
        #pragma unroll
        for(int k=0;k<8;++k){
            float4 e = slab[k*32 + lane];
            if(d4[k].x <= ma) a0 += e.x;
            if(d4[k].y <= ma) a1 += e.y;
            if(d4[k].z <= ma) a2 += e.z;
            if(d4[k].w <= ma) a3 += e.w;
            if(d4[k].x <= mb) b0 += e.x;
            if(d4[k].y <= mb) b1 += e.y;
            if(d4[k].z <= mb) b2 += e.z;
            if(d4[k].w <= mb) b3 += e.w;
        }
        unsigned qa = __float2uint_rz(((a0+a1)+(a2+a3)) * QSCALE);
        unsigned qb = __float2uint_rz(((b0+b1)+(b2+b3)) * QSCALE);
        unsigned sa = reduxAddU(qa);
        unsigned sb = reduxAddU(qb);
        if(sa > threshi){ fhi = ma; shi = sa; }
        else if(sb > threshi){ flo = ma; slo = sa; fhi = mb; shi = sb; }
        else { flo = mb; slo = sb; }
    }
    // phase 2: element stepping — d* = smallest element crossing the threshold
    float tlo = flo;
    bool done = false;
    #pragma unroll 1
    for(int step = 0; step < 10 && !done; ++step){
        float cmin = 3.4e38f;
        #pragma unroll
        for(int k=0;k<8;++k){
            if(d4[k].x > flo) cmin = fminf(cmin, d4[k].x);
            if(d4[k].y > flo) cmin = fminf(cmin, d4[k].y);
            if(d4[k].z > flo) cmin = fminf(cmin, d4[k].z);
            if(d4[k].w > flo) cmin = fminf(cmin, d4[k].w);
        }
        cmin = reduxMinF(cmin);
        if(cmin > fhi){ tlo = flo; done = true; break; }
        unsigned si = fullProbe(cmin);
        if(si > threshi){
            tlo = funkey(fkey(cmin) - 1u);   // prevfloat(cmin)
            done = true;
        } else {
            flo = cmin; slo = si;
        }
    }
    if(!done){
        unsigned lo = fkey(flo), hi = fkey(fhi);
        #pragma unroll 1
        for(int guard = 0; guard < 40 && (hi - lo > 1u); ++guard){
            unsigned midb = lo + ((hi - lo) >> 1);
            unsigned si = fullProbe(funkey(midb));
            if(si > threshi) hi = midb; else lo = midb;
        }
        tlo = funkey(lo);
    }
    // merged per-row threshold: d < Tc + BETA*(1-d/dmax)*decay  <=>  d < dT
    float bd = BETA*decay;
    float rdmax = 1.0f / mx;
    float dT = fmaxf((Tc + bd) / (1.0f + bd*rdmax), 1e-30f);
    float dTexcl = __uint_as_float(__float_as_uint(dT) - 1u);  // prevfloat(dT), dT>0
    float cutoff = fminf(tlo, dTexcl);

    const float4* Grow = (const float4*)(g_G + off);
    float4 p4[8];
    float lmax = 0.0f;   // logits are (sel? G : 0); max includes 0
    #pragma unroll
    for(int k=0;k<8;++k){
        float4 gg = Grow[k*32 + lane];
        float4 dd = d4[k];
        float lx = (dd.x <= cutoff) ? gg.x : 0.f;
        float ly = (dd.y <= cutoff) ? gg.y : 0.f;
        float lz = (dd.z <= cutoff) ? gg.z : 0.f;
        float lw = (dd.w <= cutoff) ? gg.w : 0.f;
        p4[k] = make_float4(lx,ly,lz,lw);
        lmax = fmaxf(lmax, fmaxf(fmaxf(lx,ly), fmaxf(lz,lw)));
    }
    lmax = reduxMaxF(lmax);
    float Zs = 0.f;
    #pragma unroll
    for(int k=0;k<8;++k){
        float ex = __expf(p4[k].x - lmax);
        float ey = __expf(p4[k].y - lmax);
        float ez = __expf(p4[k].z - lmax);
        float ew = __expf(p4[k].w - lmax);
        p4[k] = make_float4(ex,ey,ez,ew);
        Zs += ex+ey+ez+ew;
    }
    Zs = warpRedSum(Zs);
    float inv = 1.0f / Zs;
    // overwrite slab with normalized probs, then one block reduce to g_S
    #pragma unroll
    for(int k=0;k<8;++k){
        float4 v = p4[k];
        v.x *= inv; v.y *= inv; v.z *= inv; v.w *= inv;
        slab[k*32 + lane] = v;
    }
    __syncthreads();
    float4* Srow = (float4*)(g_S + ((size_t)(b*N + i))*3*N);
    #pragma unroll 1
    for(int t4 = tid; t4 < 768; t4 += 288){
        int hh = t4 >> 8, j4 = t4 & 255;
        float4 a0 = ((const float4*)sAcc9[0*3+hh])[j4];
        float4 a1 = ((const float4*)sAcc9[1*3+hh])[j4];
        float4 a2 = ((const float4*)sAcc9[2*3+hh])[j4];
        Srow[t4] = make_float4(a0.x+a1.x+a2.x, a0.y+a1.y+a2.y,
                               a0.z+a1.z+a2.z, a0.w+a1.w+a2.w);
    }
}

// ---------- final: o[b][c][i] += sum_j S[b][i][hN+j] f[h][b][j][c] ----------
__global__ void k_final3(float* __restrict__ out){
    int b = blockIdx.y, h = blockIdx.z;
    int i0 = blockIdx.x * 16;
    __shared__ float sST[64][18];   // [k][i], row-pairs contiguous for f32x2
    __shared__ float sF[64][65];
    int tid = threadIdx.x;
    int c = tid & 63, iq = tid >> 6;
    ull acc2[2] = {0ull, 0ull};
    #pragma unroll 1
    for(int kk2 = 0; kk2 < 16; ++kk2){
        {
            int r = tid >> 4, kb = (tid & 15)*4;
            const float* sp = g_S + ((size_t)(b*N + i0 + r))*3*N + h*N + kk2*64 + kb;
            float4 v = *(const float4*)sp;
            sST[kb+0][r] = v.x; sST[kb+1][r] = v.y;
            sST[kb+2][r] = v.z; sST[kb+3][r] = v.w;
        }
        {
            int j0 = kk2*64;
            const float* fp = g_f + ((size_t)(h*BATCH + b)*N + j0)*C;
            #pragma unroll
            for(int uu=0; uu<16; ++uu){
                int t = tid + uu*256;
                int r = t >> 6, cc = t & 63;
                sF[r][cc] = fp[r*C + cc];
            }
        }
        __syncthreads();
        #pragma unroll 8
        for(int k = 0; k < 64; ++k){
            ull fvd = pk2(sF[k][c]);
            ull r01 = *(const ull*)&sST[k][iq*4];
            ull r23 = *(const ull*)&sST[k][iq*4+2];
            ffma2(acc2[0], r01, fvd);
            ffma2(acc2[1], r23, fvd);
        }
        __syncthreads();
    }
    float2 a01 = up2(acc2[0]), a23 = up2(acc2[1]);
    float* ob = out + (size_t)b*C*N + (size_t)c*N + i0 + iq*4;
    atomicAdd(ob+0, a01.x);
    atomicAdd(ob+1, a01.y);
    atomicAdd(ob+2, a23.x);
    atomicAdd(ob+3, a23.y);
}

extern "C" void kernel_launch(void* const* d_in, const int* in_sizes, int n_in,
                              void* d_out, int out_size){
    const float* x1 = (const float*)d_in[0];
    const float* x2 = (const float*)d_in[1];
    const float* x3 = (const float*)d_in[2];
    const float* w1 = (const float*)d_in[3];
    const float* b1 = (const float*)d_in[4];
    const float* w2 = (const float*)d_in[5];
    const float* b2 = (const float*)d_in[6];
    const float* w3 = (const float*)d_in[7];
    const float* b3 = (const float*)d_in[8];
    float* out = (float*)d_out;

    static int smem_set = 0;
    if(!smem_set){
        cudaFuncSetAttribute(k_gemm_all, cudaFuncAttributeMaxDynamicSharedMemorySize, 65536);
        smem_set = 1;
    }

    k_front<<<225, 256>>>(x1, x2, x3, out);
    k_mid<<<120, 256>>>(w1, b1, w2, b2, w3, b3);
    k_gemm_all<<<dim3(64, 24), 256, 65536>>>();
    k_fa<<<dim3(N, BATCH), 288>>>();
    k_final3<<<dim3(64, BATCH, 3), 256>>>(out);
}

// round 16
// speedup vs baseline: 1.1533x; 1.0452x over previous
#include <cuda_runtime.h>
#include <math.h>

#define N 1024
#define C 64
#define BATCH 2
#define NMAT 18   // 9 pairs x 2 batches

typedef unsigned long long ull;

__device__ float g_D[(size_t)NMAT * N * N];      // distances -> adjacency source
__device__ float g_G[(size_t)NMAT * N * N];      // p_g @ p_h^T logit matrices
__device__ float g_S[(size_t)BATCH * N * 3 * N]; // summed attention [b][i][3N]
__device__ float g_f [3 * BATCH * N * C];        // features [a][b][i][c]
__device__ float g_fT[3 * BATCH * C * N];        // features [a][b][c][i]
__device__ float g_pT[3 * BATCH * C * N];        // projected features [a][b][o][i]
__device__ float g_sq[3 * BATCH * N];            // squared norms
__device__ float g_rn[3 * BATCH * N];            // 1/max(norm,1e-12)
__device__ double g_stats[NMAT * 2];             // sum, sumsq per matrix

// ---------- f32x2 helpers ----------
__device__ __forceinline__ ull pk2(float x){
    ull r; asm("mov.b64 %0, {%1, %1};" : "=l"(r) : "f"(x)); return r;
}
__device__ __forceinline__ ull pk2f(float x, float y){
    ull r; asm("mov.b64 %0, {%1, %2};" : "=l"(r) : "f"(x), "f"(y)); return r;
}
__device__ __forceinline__ void ffma2(ull &d, ull a, ull b){
    asm("fma.rn.f32x2 %0, %1, %2, %0;" : "+l"(d) : "l"(a), "l"(b));
}
__device__ __forceinline__ float2 up2(ull v){
    float2 f; asm("mov.b64 {%0, %1}, %2;" : "=f"(f.x), "=f"(f.y) : "l"(v)); return f;
}
__device__ __forceinline__ float fsqrt_ap(float x){
    float r; asm("sqrt.approx.f32 %0, %1;" : "=f"(r) : "f"(x)); return r;
}

// ---------- warp reductions ----------
__device__ __forceinline__ float warpRedSum(float v){
    #pragma unroll
    for(int o=16;o;o>>=1) v += __shfl_xor_sync(0xffffffffu, v, o);
    return v;
}
// order-preserving float<->uint keys (exact for all floats incl. negatives)
__device__ __forceinline__ unsigned fkey(float f){
    unsigned b = __float_as_uint(f);
    return (b & 0x80000000u) ? ~b : (b | 0x80000000u);
}
__device__ __forceinline__ float funkey(unsigned k){
    unsigned b = (k & 0x80000000u) ? (k ^ 0x80000000u) : ~k;
    return __uint_as_float(b);
}
// single-instruction integer warp reductions (sm_80+; f32 redux doesn't exist on sm_103)
__device__ __forceinline__ unsigned reduxAddU(unsigned v){
    unsigned r; asm("redux.sync.add.u32 %0, %1, 0xffffffff;" : "=r"(r) : "r"(v)); return r;
}
__device__ __forceinline__ unsigned reduxMaxU(unsigned v){
    unsigned r; asm("redux.sync.max.u32 %0, %1, 0xffffffff;" : "=r"(r) : "r"(v)); return r;
}
__device__ __forceinline__ unsigned reduxMinU(unsigned v){
    unsigned r; asm("redux.sync.min.u32 %0, %1, 0xffffffff;" : "=r"(r) : "r"(v)); return r;
}
__device__ __forceinline__ float reduxMaxF(float v){ return funkey(reduxMaxU(fkey(v))); }
__device__ __forceinline__ float reduxMinF(float v){ return funkey(reduxMinU(fkey(v))); }

__device__ __forceinline__ float blockRedSum(float v, float* sm){
    int tid=threadIdx.x, lane=tid&31, w=tid>>5;
    v = warpRedSum(v);
    if(lane==0) sm[w]=v;
    __syncthreads();
    if(w==0){
        float x = (lane<8)? sm[lane] : 0.0f;
        x = warpRedSum(x);
        if(lane==0) sm[0]=x;
    }
    __syncthreads();
    float r = sm[0];
    __syncthreads();
    return r;
}

// ---------- front: transpose + norms + projection + zero-out + zero-stats ----------
// bx in [0,96): 64x64 tile transpose + norms + W-projection; [96,224): zero out; 224: stats.
__global__ void k_front(const float* __restrict__ x1, const float* __restrict__ x2,
                        const float* __restrict__ x3,
                        const float* __restrict__ w1, const float* __restrict__ b1,
                        const float* __restrict__ w2, const float* __restrict__ b2,
                        const float* __restrict__ w3, const float* __restrict__ b3,
                        float* __restrict__ out){
    __shared__ float sm[64][65];   // [c][i]
    __shared__ float sw[64][66];   // [c][o] = W[o][c]
    __shared__ float sb[64];
    int bx = blockIdx.x, tid = threadIdx.x;
    if(bx < 96){
        int ab = bx >> 4; int a = ab>>1, b = ab&1;
        int i0 = (bx & 15) * 64;
        const float4* x4 = (const float4*)((a==0)? x1 : ((a==1)? x2 : x3));
        const float* W  = (a==0)? w1 : ((a==1)? w2 : w3);
        const float* Bv = (a==0)? b1 : ((a==1)? b2 : b3);
        float4* fT4 = (float4*)g_fT;
        float4* f4  = (float4*)g_f;
        int q = tid & 15, r = tid >> 4;
        #pragma unroll
        for(int u = 0; u < 4; ++u){
            int c = u*16 + r;
            float4 v = x4[(b*C + c)*256 + (i0>>2) + q];
            fT4[(ab*C + c)*256 + (i0>>2) + q] = v;
            sm[c][q*4+0] = v.x;
            sm[c][q*4+1] = v.y;
            sm[c][q*4+2] = v.z;
            sm[c][q*4+3] = v.w;
        }
        for(int t = tid; t < 4096; t += 256){
            int o = t >> 6, c = t & 63;
            sw[c][o] = W[t];
        }
        if(tid < 64) sb[tid] = Bv[tid];
        __syncthreads();
        // transposed store of features
        {
            int c4 = q * 4;
            #pragma unroll
            for(int u = 0; u < 4; ++u){
                int il = u*16 + r;
                float4 o4 = make_float4(sm[c4][il], sm[c4+1][il], sm[c4+2][il], sm[c4+3][il]);
                f4[((size_t)(ab*N) + i0 + il)*16 + q] = o4;
            }
        }
        // norms (threads 0..63, i = tid)
        if(tid < 64){
            int i = tid;
            float s = 0.f;
            #pragma unroll 8
            for(int c = 0; c < 64; ++c){ float v = sm[c][i]; s += v*v; }
            g_sq[ab*N + i0 + i] = s;
            g_rn[ab*N + i0 + i] = 1.0f / fmaxf(sqrtf(s), 1e-12f);
        }
        // projection: p[o][il] = sb[o] + sum_c sm[c][il]*sw[c][o]
        {
            int o = tid & 63, iq = tid >> 6;
            #pragma unroll 1
            for(int rr = 0; rr < 16; ++rr){
                int il = iq*16 + rr;
                float acc = sb[o];
                #pragma unroll
                for(int c = 0; c < 64; ++c) acc += sm[c][il] * sw[c][o];
                g_pT[((size_t)(ab*C) + o)*N + i0 + il] = acc;
            }
        }
    } else if(bx < 224){
        int t = (bx - 96)*256 + tid;
        ((float4*)out)[t] = make_float4(0.f,0.f,0.f,0.f);
    } else {
        if(tid < NMAT*2) g_stats[tid] = 0.0;
    }
}

// ---------- merged symmetric-aware gemm (dist + logits in one launch) ----------
__global__ void __launch_bounds__(256, 2) k_gemm_all(){
    extern __shared__ float sm[];
    float* sA = sm;              // [64][128] [c][i]
    float* sB = sm + 64*128;     // [64][128] [c][j]
    __shared__ float sred[32];
    const int GU[6] = {0,1,2,0,0,1};
    const int HU[6] = {0,1,2,1,2,2};
    int y = blockIdx.y;
    int kind = (y >= 12) ? 1 : 0;            // 0: dist, 1: logits
    int r0 = y - kind*12;
    int b = r0 & 1, u = r0 >> 1;
    int g = GU[u], h = HU[u];
    bool sym = (u < 3);
    int ti = blockIdx.x >> 3, tj = blockIdx.x & 7;
    if(sym && ti > tj) return;
    int i0 = ti*128, j0 = tj*128;
    bool mir = (!sym) || (ti < tj);
    const float* srcT = kind ? g_pT : g_fT;
    const float4* Ap = (const float4*)(srcT + (size_t)(g*BATCH + b)*C*N);
    const float4* Bp = (const float4*)(srcT + (size_t)(h*BATCH + b)*C*N);
    int tid = threadIdx.x;
    #pragma unroll
    for(int uu = 0; uu < 8; ++uu){
        int idx = tid + uu*256;
        int c = idx >> 5, q = idx & 31;
        ((float4*)(sA + c*128))[q] = Ap[c*256 + (i0>>2) + q];
        ((float4*)(sB + c*128))[q] = Bp[c*256 + (j0>>2) + q];
    }
    __syncthreads();
    int tx = tid & 15, ty = tid >> 4;
    ull acc[4][8];
    #pragma unroll
    for(int rr=0;rr<4;++rr)
        #pragma unroll
        for(int s=0;s<8;++s) acc[rr][s] = 0ull;
    #pragma unroll 8
    for(int c = 0; c < 64; ++c){
        const float* pa = sA + c*128 + ty*8;
        const float* pb = sB + c*128 + tx*8;
        ull a2[4];
        a2[0] = *(const ull*)(pa);
        a2[1] = *(const ull*)(pa+2);
        a2[2] = *(const ull*)(pa+4);
        a2[3] = *(const ull*)(pa+6);
        float4 b0 = *(const float4*)(pb);
        float4 b1 = *(const float4*)(pb+4);
        ull bd[8];
        bd[0]=pk2(b0.x); bd[1]=pk2(b0.y); bd[2]=pk2(b0.z); bd[3]=pk2(b0.w);
        bd[4]=pk2(b1.x); bd[5]=pk2(b1.y); bd[6]=pk2(b1.z); bd[7]=pk2(b1.w);
        #pragma unroll
        for(int rr=0;rr<4;++rr)
            #pragma unroll
            for(int s=0;s<8;++s) ffma2(acc[rr][s], a2[rr], bd[s]);
    }
    int mfwd = (g*3 + h)*2 + b;
    int mmir = (h*3 + g)*2 + b;
    float* dfwd = (kind ? g_G : g_D) + (size_t)mfwd * N * N;
    float* dmir = (kind ? g_G : g_D) + (size_t)mmir * N * N;
    float s1 = 0.f, s2 = 0.f;
    if(kind == 0){
        float qi[8], qj[8];
        int ib = (g*BATCH+b)*N, jb = (h*BATCH+b)*N;
        #pragma unroll
        for(int uu=0;uu<8;++uu){
            qi[uu] = sym ? g_sq[ib + i0 + ty*8 + uu] : g_rn[ib + i0 + ty*8 + uu];
            qj[uu] = sym ? g_sq[jb + j0 + tx*8 + uu] : g_rn[jb + j0 + tx*8 + uu];
        }
        #pragma unroll
        for(int rr=0;rr<4;++rr){
            #pragma unroll
            for(int s=0;s<8;++s){
                float2 t = up2(acc[rr][s]);
                float v0, v1;
                if(sym){
                    v0 = fsqrt_ap(fmaxf(qi[2*rr]   + qj[s] - 2.0f*t.x, 1e-12f));
                    v1 = fsqrt_ap(fmaxf(qi[2*rr+1] + qj[s] - 2.0f*t.y, 1e-12f));
                } else {
                    v0 = 1.0f - t.x*qi[2*rr]  *qj[s];
                    v1 = 1.0f - t.y*qi[2*rr+1]*qj[s];
                }
                s1 += v0 + v1; s2 += v0*v0 + v1*v1;
                acc[rr][s] = pk2f(v0, v1);
            }
        }
    }
    #pragma unroll
    for(int ii=0; ii<8; ++ii){
        int rr = ii>>1, hi = ii&1;
        float o[8];
        #pragma unroll
        for(int s=0;s<8;++s){
            float2 t = up2(acc[rr][s]);
            o[s] = hi ? t.y : t.x;
        }
        float* dr = dfwd + (size_t)(i0 + ty*8 + ii)*N + j0 + tx*8;
        *(float4*)(dr)   = make_float4(o[0],o[1],o[2],o[3]);
        *(float4*)(dr+4) = make_float4(o[4],o[5],o[6],o[7]);
    }
    if(kind == 0){
        float t1 = blockRedSum(s1, sred);
        float t2 = blockRedSum(s2, sred);
        if(tid == 0){
            double wgt = (sym && ti < tj) ? 2.0 : 1.0;
            atomicAdd(&g_stats[mfwd*2+0], (double)t1 * wgt);
            atomicAdd(&g_stats[mfwd*2+1], (double)t2 * wgt);
            if(!sym){
                atomicAdd(&g_stats[mmir*2+0], (double)t1);
                atomicAdd(&g_stats[mmir*2+1], (double)t2);
            }
        }
    }
    if(mir){
        float4* st4 = (float4*)sm;   // [128][16] float4, XOR-swizzled
        #pragma unroll 1
        for(int st = 0; st < 2; ++st){
            __syncthreads();
            if((ty>>3) == st){
                int cb = (ty & 7)*2;
                #pragma unroll
                for(int s = 0; s < 8; ++s){
                    int jj = tx*8 + s;
                    float2 p0 = up2(acc[0][s]), p1 = up2(acc[1][s]);
                    float2 p2 = up2(acc[2][s]), p3 = up2(acc[3][s]);
                    st4[jj*16 + ((cb+0) ^ tx)] = make_float4(p0.x,p0.y,p1.x,p1.y);
                    st4[jj*16 + ((cb+1) ^ tx)] = make_float4(p2.x,p2.y,p3.x,p3.y);
                }
            }
            __syncthreads();
            #pragma unroll
            for(int u2 = 0; u2 < 8; ++u2){
                int idx = tid + u2*256;
                int jj = idx >> 4, c4 = idx & 15;
                float4 val = st4[jj*16 + (c4 ^ ((jj>>3) & 15))];
                *(float4*)&dmir[(size_t)(j0+jj)*N + i0 + st*64 + c4*4] = val;
            }
        }
    }
}

// ---------- fused adjacency + attention (e in smem slab, 3 blocks/SM) ----------
__global__ void __launch_bounds__(288, 3) k_fa(){
    const float ETA = 1.0f, ALPHA = 0.08f, BETA = 0.01f, INV_TAU = 0.1f, PROB_TH = 0.8f;
    const float QSCALE = 1048576.0f;   // 2^20
    int i = blockIdx.x, b = blockIdx.y;
    int tid = threadIdx.x, w = tid >> 5, lane = tid & 31;
    __shared__ float sAcc9[9][N];      // 36KB: e-values during bisection, p-values at end

    int m = w*BATCH + b;
    size_t off = (size_t)m*N*N + (size_t)i*N;
    const float4* Drow = (const float4*)(g_D + off);
    float4* slab = (float4*)sAcc9[w];   // this warp's private 4KB
    float4 d4[8];
    #pragma unroll
    for(int k=0;k<8;++k) d4[k] = Drow[k*32 + lane];
    float mx = -1e30f, mn = 1e30f;
    #pragma unroll
    for(int k=0;k<8;++k){
        mx = fmaxf(mx, fmaxf(fmaxf(d4[k].x,d4[k].y), fmaxf(d4[k].z,d4[k].w)));
        mn = fminf(mn, fminf(fminf(d4[k].x,d4[k].y), fminf(d4[k].z,d4[k].w)));
    }
    mx = reduxMaxF(mx);
    mn = reduxMinF(mn);
    float Z = 0.f, num = 0.f;
    #pragma unroll
    for(int k=0;k<8;++k){
        float ex = __expf((mn - d4[k].x)*INV_TAU);
        float ey = __expf((mn - d4[k].y)*INV_TAU);
        float ez = __expf((mn - d4[k].z)*INV_TAU);
        float ew = __expf((mn - d4[k].w)*INV_TAU);
        slab[k*32 + lane] = make_float4(ex,ey,ez,ew);   // e -> smem (warp-private)
        Z += ex+ey+ez+ew;
        num += ex*(d4[k].x-mn) + ey*(d4[k].y-mn) + ez*(d4[k].z-mn) + ew*(d4[k].w-mn);
    }
    Z   = warpRedSum(Z);
    num = warpRedSum(num);
    float entropy = logf(Z) + num*INV_TAU/Z;
    float decay = __expf(-ETA*entropy);
    double ssum = g_stats[m*2+0], ssq = g_stats[m*2+1];
    const double N2 = (double)N*(double)N;
    double mu  = ssum / N2;
    double var = (ssq - ssum*ssum/N2) / (N2 - 1.0);
    float sigma = (float)sqrt(fmax(var, 0.0));
    float Tc = (float)mu + ALPHA*sigma;
    unsigned threshi = (unsigned)(PROB_TH * Z * QSCALE);

    // single full probe (quantized, monotone); e read from slab
    auto fullProbe = [&](float mid)->unsigned{
        float s0=0,s1=0,s2=0,s3=0;
        #pragma unroll
        for(int k=0;k<8;++k){
            float4 e = slab[k*32 + lane];
            if(d4[k].x <= mid) s0 += e.x;
            if(d4[k].y <= mid) s1 += e.y;
            if(d4[k].z <= mid) s2 += e.z;
            if(d4[k].w <= mid) s3 += e.w;
        }
        return reduxAddU(__float2uint_rz(((s0+s1)+(s2+s3)) * QSCALE));
    };

    // phase 1: 7 dual-probe rounds (interp + midpoint fused into one scan)
    float flo = 0.0f, fhi = mx;
    unsigned slo = 0u, shi = (unsigned)(Z * QSCALE) + 2048u;
    #pragma unroll 1
    for(int it = 0; it < 7; ++it){
        float span = fhi - flo;
        float frac = (float)(threshi - slo) / fmaxf((float)(shi - slo), 1.0f);
        float mi  = flo + span*frac;
        float mid = flo + 0.5f*span;
        float ma = fminf(mi, mid), mb = fmaxf(mi, mid);
        float a0=0,a1=0,a2=0,a3=0, b0=0,b1=0,b2=0,b3=0;
        #pragma unroll
        for(int k=0;k<8;++k){
            float4 e = slab[k*32 + lane];
            if(d4[k].x <= ma) a0 += e.x;
            if(d4[k].y <= ma) a1 += e.y;
            if(d4[k].z <= ma) a2 += e.z;
            if(d4[k].w <= ma) a3 += e.w;
            if(d4[k].x <= mb) b0 += e.x;
            if(d4[k].y <= mb) b1 += e.y;
            if(d4[k].z <= mb) b2 += e.z;
            if(d4[k].w <= mb) b3 += e.w;
        }
        unsigned qa = __float2uint_rz(((a0+a1)+(a2+a3)) * QSCALE);
        unsigned qb = __float2uint_rz(((b0+b1)+(b2+b3)) * QSCALE);
        unsigned sa = reduxAddU(qa);
        unsigned sb2 = reduxAddU(qb);
        if(sa > threshi){ fhi = ma; shi = sa; }
        else if(sb2 > threshi){ flo = ma; slo = sa; fhi = mb; shi = sb2; }
        else { flo = mb; slo = sb2; }
    }
    // phase 2: element stepping — d* = smallest element crossing the threshold
    float tlo = flo;
    bool done = false;
    #pragma unroll 1
    for(int step = 0; step < 10 && !done; ++step){
        float cmin = 3.4e38f;
        #pragma unroll
        for(int k=0;k<8;++k){
            if(d4[k].x > flo) cmin = fminf(cmin, d4[k].x);
            if(d4[k].y > flo) cmin = fminf(cmin, d4[k].y);
            if(d4[k].z > flo) cmin = fminf(cmin, d4[k].z);
            if(d4[k].w > flo) cmin = fminf(cmin, d4[k].w);
        }
        cmin = reduxMinF(cmin);
        if(cmin > fhi){ tlo = flo; done = true; break; }
        unsigned si = fullProbe(cmin);
        if(si > threshi){
            tlo = funkey(fkey(cmin) - 1u);   // prevfloat(cmin)
            done = true;
        } else {
            flo = cmin; slo = si;
        }
    }
    if(!done){
        unsigned lo = fkey(flo), hi = fkey(fhi);
        #pragma unroll 1
        for(int guard = 0; guard < 40 && (hi - lo > 1u); ++guard){
            unsigned midb = lo + ((hi - lo) >> 1);
            unsigned si = fullProbe(funkey(midb));
            if(si > threshi) hi = midb; else lo = midb;
        }
        tlo = funkey(lo);
    }
    // merged per-row threshold: d < Tc + BETA*(1-d/dmax)*decay  <=>  d < dT
    float bd = BETA*decay;
    float rdmax = 1.0f / mx;
    float dT = fmaxf((Tc + bd) / (1.0f + bd*rdmax), 1e-30f);
    float dTexcl = __uint_as_float(__float_as_uint(dT) - 1u);  // prevfloat(dT), dT>0
    float cutoff = fminf(tlo, dTexcl);

    const float4* Grow = (const float4*)(g_G + off);
    float4 p4[8];
    float lmax = 0.0f;   // logits are (sel? G : 0); max includes 0
    #pragma unroll
    for(int k=0;k<8;++k){
        float4 gg = Grow[k*32 + lane];
        float4 dd = d4[k];
        float lx = (dd.x <= cutoff) ? gg.x : 0.f;
        float ly = (dd.y <= cutoff) ? gg.y : 0.f;
        float lz = (dd.z <= cutoff) ? gg.z : 0.f;
        float lw = (dd.w <= cutoff) ? gg.w : 0.f;
        p4[k] = make_float4(lx,ly,lz,lw);
        lmax = fmaxf(lmax, fmaxf(fmaxf(lx,ly), fmaxf(lz,lw)));
    }
    lmax = reduxMaxF(lmax);
    float Zs = 0.f;
    #pragma unroll
    for(int k=0;k<8;++k){
        float ex = __expf(p4[k].x - lmax);
        float ey = __expf(p4[k].y - lmax);
        float ez = __expf(p4[k].z - lmax);
        float ew = __expf(p4[k].w - lmax);
        p4[k] = make_float4(ex,ey,ez,ew);
        Zs += ex+ey+ez+ew;
    }
    Zs = warpRedSum(Zs);
    float inv = 1.0f / Zs;
    // overwrite slab with normalized probs, then one block reduce to g_S
    #pragma unroll
    for(int k=0;k<8;++k){
        float4 v = p4[k];
        v.x *= inv; v.y *= inv; v.z *= inv; v.w *= inv;
        slab[k*32 + lane] = v;
    }
    __syncthreads();
    float4* Srow = (float4*)(g_S + ((size_t)(b*N + i))*3*N);
    #pragma unroll 1
    for(int t4 = tid; t4 < 768; t4 += 288){
        int hh = t4 >> 8, j4 = t4 & 255;
        float4 a0 = ((const float4*)sAcc9[0*3+hh])[j4];
        float4 a1 = ((const float4*)sAcc9[1*3+hh])[j4];
        float4 a2 = ((const float4*)sAcc9[2*3+hh])[j4];
        Srow[t4] = make_float4(a0.x+a1.x+a2.x, a0.y+a1.y+a2.y,
                               a0.z+a1.z+a2.z, a0.w+a1.w+a2.w);
    }
}

// ---------- final: o[b][c][i] += sum_j S[b][i][hN+j] f[h][b][j][c], 32-row tiles ----------
__global__ void k_final3(float* __restrict__ out){
    int b = blockIdx.y, h = blockIdx.z;
    int i0 = blockIdx.x * 32;
    __shared__ float sST[64][34];   // [k][i]
    __shared__ float sF[64][65];
    int tid = threadIdx.x;
    int c = tid & 63, iq = tid >> 6;   // iq in 0..3, 8 i's per thread
    ull acc2[4] = {0ull, 0ull, 0ull, 0ull};
    #pragma unroll 1
    for(int kk2 = 0; kk2 < 16; ++kk2){
        {
            int r = tid >> 3, kb = (tid & 7)*8;
            const float* sp = g_S + ((size_t)(b*N + i0 + r))*3*N + h*N + kk2*64 + kb;
            float4 v0 = *(const float4*)sp;
            float4 v1 = *(const float4*)(sp+4);
            sST[kb+0][r] = v0.x; sST[kb+1][r] = v0.y;
            sST[kb+2][r] = v0.z; sST[kb+3][r] = v0.w;
            sST[kb+4][r] = v1.x; sST[kb+5][r] = v1.y;
            sST[kb+6][r] = v1.z; sST[kb+7][r] = v1.w;
        }
        {
            int j0 = kk2*64;
            const float* fp = g_f + ((size_t)(h*BATCH + b)*N + j0)*C;
            #pragma unroll
            for(int uu=0; uu<16; ++uu){
                int t = tid + uu*256;
                int r = t >> 6, cc = t & 63;
                sF[r][cc] = fp[r*C + cc];
            }
        }
        __syncthreads();
        #pragma unroll 8
        for(int k = 0; k < 64; ++k){
            ull fvd = pk2(sF[k][c]);
            ull r0 = *(const ull*)&sST[k][iq*8];
            ull r1 = *(const ull*)&sST[k][iq*8+2];
            ull r2 = *(const ull*)&sST[k][iq*8+4];
            ull r3 = *(const ull*)&sST[k][iq*8+6];
            ffma2(acc2[0], r0, fvd);
            ffma2(acc2[1], r1, fvd);
            ffma2(acc2[2], r2, fvd);
            ffma2(acc2[3], r3, fvd);
        }
        __syncthreads();
    }
    float2 a0 = up2(acc2[0]), a1 = up2(acc2[1]);
    float2 a2 = up2(acc2[2]), a3 = up2(acc2[3]);
    float* ob = out + (size_t)b*C*N + (size_t)c*N + i0 + iq*8;
    atomicAdd(ob+0, a0.x); atomicAdd(ob+1, a0.y);
    atomicAdd(ob+2, a1.x); atomicAdd(ob+3, a1.y);
    atomicAdd(ob+4, a2.x); atomicAdd(ob+5, a2.y);
    atomicAdd(ob+6, a3.x); atomicAdd(ob+7, a3.y);
}

extern "C" void kernel_launch(void* const* d_in, const int* in_sizes, int n_in,
                              void* d_out, int out_size){
    const float* x1 = (const float*)d_in[0];
    const float* x2 = (const float*)d_in[1];
    const float* x3 = (const float*)d_in[2];
    const float* w1 = (const float*)d_in[3];
    const float* b1 = (const float*)d_in[4];
    const float* w2 = (const float*)d_in[5];
    const float* b2 = (const float*)d_in[6];
    const float* w3 = (const float*)d_in[7];
    const float* b3 = (const float*)d_in[8];
    float* out = (float*)d_out;

    static int smem_set = 0;
    if(!smem_set){
        cudaFuncSetAttribute(k_gemm_all, cudaFuncAttributeMaxDynamicSharedMemorySize, 65536);
        smem_set = 1;
    }

    k_front<<<225, 256>>>(x1, x2, x3, w1, b1, w2, b2, w3, b3, out);
    k_gemm_all<<<dim3(64, 24), 256, 65536>>>();
    k_fa<<<dim3(N, BATCH), 288>>>();
    k_final3<<<dim3(32, BATCH, 3), 256>>>(out);
}

// round 17
// speedup vs baseline: 1.2030x; 1.0431x over previous
#include <cuda_runtime.h>
#include <math.h>

#define N 1024
#define C 64
#define BATCH 2
#define NMAT 18   // 9 pairs x 2 batches

typedef unsigned long long ull;

__device__ float g_D[(size_t)NMAT * N * N];      // distances -> adjacency source
__device__ float g_G[(size_t)NMAT * N * N];      // p_g @ p_h^T logit matrices
__device__ float g_S[(size_t)BATCH * N * 3 * N]; // summed attention [b][i][3N]
__device__ float g_f [3 * BATCH * N * C];        // features [a][b][i][c]
__device__ float g_fT[3 * BATCH * C * N];        // features [a][b][c][i]
__device__ float g_pT[3 * BATCH * C * N];        // projected features [a][b][o][i]
__device__ float g_sq[3 * BATCH * N];            // squared norms
__device__ float g_rn[3 * BATCH * N];            // 1/max(norm,1e-12)
__device__ double g_stats[NMAT * 2];             // sum, sumsq per matrix

// ---------- f32x2 helpers ----------
__device__ __forceinline__ ull pk2(float x){
    ull r; asm("mov.b64 %0, {%1, %1};" : "=l"(r) : "f"(x)); return r;
}
__device__ __forceinline__ ull pk2f(float x, float y){
    ull r; asm("mov.b64 %0, {%1, %2};" : "=l"(r) : "f"(x), "f"(y)); return r;
}
__device__ __forceinline__ void ffma2(ull &d, ull a, ull b){
    asm("fma.rn.f32x2 %0, %1, %2, %0;" : "+l"(d) : "l"(a), "l"(b));
}
__device__ __forceinline__ float2 up2(ull v){
    float2 f; asm("mov.b64 {%0, %1}, %2;" : "=f"(f.x), "=f"(f.y) : "l"(v)); return f;
}
__device__ __forceinline__ float fsqrt_ap(float x){
    float r; asm("sqrt.approx.f32 %0, %1;" : "=f"(r) : "f"(x)); return r;
}

// ---------- warp reductions ----------
__device__ __forceinline__ float warpRedSum(float v){
    #pragma unroll
    for(int o=16;o;o>>=1) v += __shfl_xor_sync(0xffffffffu, v, o);
    return v;
}
// order-preserving float<->uint keys (exact for all floats incl. negatives)
__device__ __forceinline__ unsigned fkey(float f){
    unsigned b = __float_as_uint(f);
    return (b & 0x80000000u) ? ~b : (b | 0x80000000u);
}
__device__ __forceinline__ float funkey(unsigned k){
    unsigned b = (k & 0x80000000u) ? (k ^ 0x80000000u) : ~k;
    return __uint_as_float(b);
}
// single-instruction integer warp reductions (sm_80+; f32 redux doesn't exist on sm_103)
__device__ __forceinline__ unsigned reduxAddU(unsigned v){
    unsigned r; asm("redux.sync.add.u32 %0, %1, 0xffffffff;" : "=r"(r) : "r"(v)); return r;
}
__device__ __forceinline__ unsigned reduxMaxU(unsigned v){
    unsigned r; asm("redux.sync.max.u32 %0, %1, 0xffffffff;" : "=r"(r) : "r"(v)); return r;
}
__device__ __forceinline__ unsigned reduxMinU(unsigned v){
    unsigned r; asm("redux.sync.min.u32 %0, %1, 0xffffffff;" : "=r"(r) : "r"(v)); return r;
}
__device__ __forceinline__ float reduxMaxF(float v){ return funkey(reduxMaxU(fkey(v))); }
__device__ __forceinline__ float reduxMinF(float v){ return funkey(reduxMinU(fkey(v))); }

__device__ __forceinline__ float blockRedSum(float v, float* sm){
    int tid=threadIdx.x, lane=tid&31, w=tid>>5;
    v = warpRedSum(v);
    if(lane==0) sm[w]=v;
    __syncthreads();
    if(w==0){
        float x = (lane<8)? sm[lane] : 0.0f;
        x = warpRedSum(x);
        if(lane==0) sm[0]=x;
    }
    __syncthreads();
    float r = sm[0];
    __syncthreads();
    return r;
}

// ---------- front: transpose + norms + projection + zero-out + zero-stats ----------
__global__ void k_front(const float* __restrict__ x1, const float* __restrict__ x2,
                        const float* __restrict__ x3,
                        const float* __restrict__ w1, const float* __restrict__ b1,
                        const float* __restrict__ w2, const float* __restrict__ b2,
                        const float* __restrict__ w3, const float* __restrict__ b3,
                        float* __restrict__ out){
    __shared__ float sm[64][65];   // [c][i]
    __shared__ float sw[64][66];   // [c][o] = W[o][c]
    __shared__ float sb[64];
    int bx = blockIdx.x, tid = threadIdx.x;
    if(bx < 96){
        int ab = bx >> 4; int a = ab>>1, b = ab&1;
        int i0 = (bx & 15) * 64;
        const float4* x4 = (const float4*)((a==0)? x1 : ((a==1)? x2 : x3));
        const float* W  = (a==0)? w1 : ((a==1)? w2 : w3);
        const float* Bv = (a==0)? b1 : ((a==1)? b2 : b3);
        float4* fT4 = (float4*)g_fT;
        float4* f4  = (float4*)g_f;
        int q = tid & 15, r = tid >> 4;
        #pragma unroll
        for(int u = 0; u < 4; ++u){
            int c = u*16 + r;
            float4 v = x4[(b*C + c)*256 + (i0>>2) + q];
            fT4[(ab*C + c)*256 + (i0>>2) + q] = v;
            sm[c][q*4+0] = v.x;
            sm[c][q*4+1] = v.y;
            sm[c][q*4+2] = v.z;
            sm[c][q*4+3] = v.w;
        }
        for(int t = tid; t < 4096; t += 256){
            int o = t >> 6, c = t & 63;
            sw[c][o] = W[t];
        }
        if(tid < 64) sb[tid] = Bv[tid];
        __syncthreads();
        {
            int c4 = q * 4;
            #pragma unroll
            for(int u = 0; u < 4; ++u){
                int il = u*16 + r;
                float4 o4 = make_float4(sm[c4][il], sm[c4+1][il], sm[c4+2][il], sm[c4+3][il]);
                f4[((size_t)(ab*N) + i0 + il)*16 + q] = o4;
            }
        }
        if(tid < 64){
            int i = tid;
            float s = 0.f;
            #pragma unroll 8
            for(int c = 0; c < 64; ++c){ float v = sm[c][i]; s += v*v; }
            g_sq[ab*N + i0 + i] = s;
            g_rn[ab*N + i0 + i] = 1.0f / fmaxf(sqrtf(s), 1e-12f);
        }
        {
            int o = tid & 63, iq = tid >> 6;
            #pragma unroll 1
            for(int rr = 0; rr < 16; ++rr){
                int il = iq*16 + rr;
                float acc = sb[o];
                #pragma unroll
                for(int c = 0; c < 64; ++c) acc += sm[c][il] * sw[c][o];
                g_pT[((size_t)(ab*C) + o)*N + i0 + il] = acc;
            }
        }
    } else if(bx < 224){
        int t = (bx - 96)*256 + tid;
        ((float4*)out)[t] = make_float4(0.f,0.f,0.f,0.f);
    } else {
        if(tid < NMAT*2) g_stats[tid] = 0.0;
    }
}

// ---------- merged symmetric-aware gemm (dist + logits in one launch) ----------
__global__ void __launch_bounds__(256, 2) k_gemm_all(){
    extern __shared__ float sm[];
    float* sA = sm;              // [64][128] [c][i]
    float* sB = sm + 64*128;     // [64][128] [c][j]
    __shared__ float sred[32];
    const int GU[6] = {0,1,2,0,0,1};
    const int HU[6] = {0,1,2,1,2,2};
    int y = blockIdx.y;
    int kind = (y >= 12) ? 1 : 0;            // 0: dist, 1: logits
    int r0 = y - kind*12;
    int b = r0 & 1, u = r0 >> 1;
    int g = GU[u], h = HU[u];
    bool sym = (u < 3);
    int ti = blockIdx.x >> 3, tj = blockIdx.x & 7;
    if(sym && ti > tj) return;
    int i0 = ti*128, j0 = tj*128;
    bool mir = (!sym) || (ti < tj);
    const float* srcT = kind ? g_pT : g_fT;
    const float4* Ap = (const float4*)(srcT + (size_t)(g*BATCH + b)*C*N);
    const float4* Bp = (const float4*)(srcT + (size_t)(h*BATCH + b)*C*N);
    int tid = threadIdx.x;
    #pragma unroll
    for(int uu = 0; uu < 8; ++uu){
        int idx = tid + uu*256;
        int c = idx >> 5, q = idx & 31;
        ((float4*)(sA + c*128))[q] = Ap[c*256 + (i0>>2) + q];
        ((float4*)(sB + c*128))[q] = Bp[c*256 + (j0>>2) + q];
    }
    __syncthreads();
    int tx = tid & 15, ty = tid >> 4;
    ull acc[4][8];
    #pragma unroll
    for(int rr=0;rr<4;++rr)
        #pragma unroll
        for(int s=0;s<8;++s) acc[rr][s] = 0ull;
    #pragma unroll 8
    for(int c = 0; c < 64; ++c){
        const float* pa = sA + c*128 + ty*8;
        const float* pb = sB + c*128 + tx*8;
        ull a2[4];
        a2[0] = *(const ull*)(pa);
        a2[1] = *(const ull*)(pa+2);
        a2[2] = *(const ull*)(pa+4);
        a2[3] = *(const ull*)(pa+6);
        float4 b0 = *(const float4*)(pb);
        float4 b1 = *(const float4*)(pb+4);
        ull bd[8];
        bd[0]=pk2(b0.x); bd[1]=pk2(b0.y); bd[2]=pk2(b0.z); bd[3]=pk2(b0.w);
        bd[4]=pk2(b1.x); bd[5]=pk2(b1.y); bd[6]=pk2(b1.z); bd[7]=pk2(b1.w);
        #pragma unroll
        for(int rr=0;rr<4;++rr)
            #pragma unroll
            for(int s=0;s<8;++s) ffma2(acc[rr][s], a2[rr], bd[s]);
    }
    int mfwd = (g*3 + h)*2 + b;
    int mmir = (h*3 + g)*2 + b;
    float* dfwd = (kind ? g_G : g_D) + (size_t)mfwd * N * N;
    float* dmir = (kind ? g_G : g_D) + (size_t)mmir * N * N;
    float s1 = 0.f, s2 = 0.f;
    if(kind == 0){
        float qi[8], qj[8];
        int ib = (g*BATCH+b)*N, jb = (h*BATCH+b)*N;
        #pragma unroll
        for(int uu=0;uu<8;++uu){
            qi[uu] = sym ? g_sq[ib + i0 + ty*8 + uu] : g_rn[ib + i0 + ty*8 + uu];
            qj[uu] = sym ? g_sq[jb + j0 + tx*8 + uu] : g_rn[jb + j0 + tx*8 + uu];
        }
        #pragma unroll
        for(int rr=0;rr<4;++rr){
            #pragma unroll
            for(int s=0;s<8;++s){
                float2 t = up2(acc[rr][s]);
                float v0, v1;
                if(sym){
                    v0 = fsqrt_ap(fmaxf(qi[2*rr]   + qj[s] - 2.0f*t.x, 1e-12f));
                    v1 = fsqrt_ap(fmaxf(qi[2*rr+1] + qj[s] - 2.0f*t.y, 1e-12f));
                } else {
                    v0 = 1.0f - t.x*qi[2*rr]  *qj[s];
                    v1 = 1.0f - t.y*qi[2*rr+1]*qj[s];
                }
                s1 += v0 + v1; s2 += v0*v0 + v1*v1;
                acc[rr][s] = pk2f(v0, v1);
            }
        }
    }
    #pragma unroll
    for(int ii=0; ii<8; ++ii){
        int rr = ii>>1, hi = ii&1;
        float o[8];
        #pragma unroll
        for(int s=0;s<8;++s){
            float2 t = up2(acc[rr][s]);
            o[s] = hi ? t.y : t.x;
        }
        float* dr = dfwd + (size_t)(i0 + ty*8 + ii)*N + j0 + tx*8;
        *(float4*)(dr)   = make_float4(o[0],o[1],o[2],o[3]);
        *(float4*)(dr+4) = make_float4(o[4],o[5],o[6],o[7]);
    }
    if(kind == 0){
        float t1 = blockRedSum(s1, sred);
        float t2 = blockRedSum(s2, sred);
        if(tid == 0){
            double wgt = (sym && ti < tj) ? 2.0 : 1.0;
            atomicAdd(&g_stats[mfwd*2+0], (double)t1 * wgt);
            atomicAdd(&g_stats[mfwd*2+1], (double)t2 * wgt);
            if(!sym){
                atomicAdd(&g_stats[mmir*2+0], (double)t1);
                atomicAdd(&g_stats[mmir*2+1], (double)t2);
            }
        }
    }
    if(mir){
        float4* st4 = (float4*)sm;   // [128][16] float4, XOR-swizzled
        #pragma unroll 1
        for(int st = 0; st < 2; ++st){
            __syncthreads();
            if((ty>>3) == st){
                int cb = (ty & 7)*2;
                #pragma unroll
                for(int s = 0; s < 8; ++s){
                    int jj = tx*8 + s;
                    float2 p0 = up2(acc[0][s]), p1 = up2(acc[1][s]);
                    float2 p2 = up2(acc[2][s]), p3 = up2(acc[3][s]);
                    st4[jj*16 + ((cb+0) ^ tx)] = make_float4(p0.x,p0.y,p1.x,p1.y);
                    st4[jj*16 + ((cb+1) ^ tx)] = make_float4(p2.x,p2.y,p3.x,p3.y);
                }
            }
            __syncthreads();
            #pragma unroll
            for(int u2 = 0; u2 < 8; ++u2){
                int idx = tid + u2*256;
                int jj = idx >> 4, c4 = idx & 15;
                float4 val = st4[jj*16 + (c4 ^ ((jj>>3) & 15))];
                *(float4*)&dmir[(size_t)(j0+jj)*N + i0 + st*64 + c4*4] = val;
            }
        }
    }
}

// ---------- fused adjacency + attention (e in smem slab, 3 blocks/SM) ----------
__global__ void __launch_bounds__(288, 3) k_fa(){
    const float ETA = 1.0f, ALPHA = 0.08f, BETA = 0.01f, INV_TAU = 0.1f, PROB_TH = 0.8f;
    const float QSCALE = 1048576.0f;   // 2^20
    int i = blockIdx.x, b = blockIdx.y;
    int tid = threadIdx.x, w = tid >> 5, lane = tid & 31;
    __shared__ float sAcc9[9][N];      // 36KB: e-values during bisection, p-values at end

    int m = w*BATCH + b;
    size_t off = (size_t)m*N*N + (size_t)i*N;
    const float4* Drow = (const float4*)(g_D + off);
    float4* slab = (float4*)sAcc9[w];   // this warp's private 4KB
    float4 d4[8];
    #pragma unroll
    for(int k=0;k<8;++k) d4[k] = Drow[k*32 + lane];
    float mx = -1e30f, mn = 1e30f;
    #pragma unroll
    for(int k=0;k<8;++k){
        mx = fmaxf(mx, fmaxf(fmaxf(d4[k].x,d4[k].y), fmaxf(d4[k].z,d4[k].w)));
        mn = fminf(mn, fminf(fminf(d4[k].x,d4[k].y), fminf(d4[k].z,d4[k].w)));
    }
    mx = reduxMaxF(mx);
    mn = reduxMinF(mn);
    float Z = 0.f, num = 0.f;
    #pragma unroll
    for(int k=0;k<8;++k){
        float ex = __expf((mn - d4[k].x)*INV_TAU);
        float ey = __expf((mn - d4[k].y)*INV_TAU);
        float ez = __expf((mn - d4[k].z)*INV_TAU);
        float ew = __expf((mn - d4[k].w)*INV_TAU);
        slab[k*32 + lane] = make_float4(ex,ey,ez,ew);   // e -> smem (warp-private)
        Z += ex+ey+ez+ew;
        num += ex*(d4[k].x-mn) + ey*(d4[k].y-mn) + ez*(d4[k].z-mn) + ew*(d4[k].w-mn);
    }
    Z   = warpRedSum(Z);
    num = warpRedSum(num);
    float entropy = logf(Z) + num*INV_TAU/Z;
    float decay = __expf(-ETA*entropy);
    double ssum = g_stats[m*2+0], ssq = g_stats[m*2+1];
    const double N2 = (double)N*(double)N;
    double mu  = ssum / N2;
    double var = (ssq - ssum*ssum/N2) / (N2 - 1.0);
    float sigma = (float)sqrt(fmax(var, 0.0));
    float Tc = (float)mu + ALPHA*sigma;
    unsigned threshi = (unsigned)(PROB_TH * Z * QSCALE);

    auto fullProbe = [&](float mid)->unsigned{
        float s0=0,s1=0,s2=0,s3=0;
        #pragma unroll
        for(int k=0;k<8;++k){
            float4 e = slab[k*32 + lane];
            if(d4[k].x <= mid) s0 += e.x;
            if(d4[k].y <= mid) s1 += e.y;
            if(d4[k].z <= mid) s2 += e.z;
            if(d4[k].w <= mid) s3 += e.w;
        }
        return reduxAddU(__float2uint_rz(((s0+s1)+(s2+s3)) * QSCALE));
    };

    float flo = 0.0f, fhi = mx;
    unsigned slo = 0u, shi = (unsigned)(Z * QSCALE) + 2048u;
    #pragma unroll 1
    for(int it = 0; it < 7; ++it){
        float span = fhi - flo;
        float frac = (float)(threshi - slo) / fmaxf((float)(shi - slo), 1.0f);
        float mi  = flo + span*frac;
        float mid = flo + 0.5f*span;
        float ma = fminf(mi, mid), mb = fmaxf(mi, mid);
        float a0=0,a1=0,a2=0,a3=0, b0=0,b1=0,b2=0,b3=0;
        #pragma unroll
        for(int k=0;k<8;++k){
            float4 e = slab[k*32 + lane];
            if(d4[k].x <= ma) a0 += e.x;
            if(d4[k].y <= ma) a1 += e.y;
            if(d4[k].z <= ma) a2 += e.z;
            if(d4[k].w <= ma) a3 += e.w;
            if(d4[k].x <= mb) b0 += e.x;
            if(d4[k].y <= mb) b1 += e.y;
            if(d4[k].z <= mb) b2 += e.z;
            if(d4[k].w <= mb) b3 += e.w;
        }
        unsigned qa = __float2uint_rz(((a0+a1)+(a2+a3)) * QSCALE);
        unsigned qb = __float2uint_rz(((b0+b1)+(b2+b3)) * QSCALE);
        unsigned sa = reduxAddU(qa);
        unsigned sb2 = reduxAddU(qb);
        if(sa > threshi){ fhi = ma; shi = sa; }
        else if(sb2 > threshi){ flo = ma; slo = sa; fhi = mb; shi = sb2; }
        else { flo = mb; slo = sb2; }
    }
    float tlo = flo;
    bool done = false;
    #pragma unroll 1
    for(int step = 0; step < 10 && !done; ++step){
        float cmin = 3.4e38f;
        #pragma unroll
        for(int k=0;k<8;++k){
            if(d4[k].x > flo) cmin = fminf(cmin, d4[k].x);
            if(d4[k].y > flo) cmin = fminf(cmin, d4[k].y);
            if(d4[k].z > flo) cmin = fminf(cmin, d4[k].z);
            if(d4[k].w > flo) cmin = fminf(cmin, d4[k].w);
        }
        cmin = reduxMinF(cmin);
        if(cmin > fhi){ tlo = flo; done = true; break; }
        unsigned si = fullProbe(cmin);
        if(si > threshi){
            tlo = funkey(fkey(cmin) - 1u);   // prevfloat(cmin)
            done = true;
        } else {
            flo = cmin; slo = si;
        }
    }
    if(!done){
        unsigned lo = fkey(flo), hi = fkey(fhi);
        #pragma unroll 1
        for(int guard = 0; guard < 40 && (hi - lo > 1u); ++guard){
            unsigned midb = lo + ((hi - lo) >> 1);
            unsigned si = fullProbe(funkey(midb));
            if(si > threshi) hi = midb; else lo = midb;
        }
        tlo = funkey(lo);
    }
    float bd = BETA*decay;
    float rdmax = 1.0f / mx;
    float dT = fmaxf((Tc + bd) / (1.0f + bd*rdmax), 1e-30f);
    float dTexcl = __uint_as_float(__float_as_uint(dT) - 1u);  // prevfloat(dT), dT>0
    float cutoff = fminf(tlo, dTexcl);

    const float4* Grow = (const float4*)(g_G + off);
    float4 p4[8];
    float lmax = 0.0f;
    #pragma unroll
    for(int k=0;k<8;++k){
        float4 gg = Grow[k*32 + lane];
        float4 dd = d4[k];
        float lx = (dd.x <= cutoff) ? gg.x : 0.f;
        float ly = (dd.y <= cutoff) ? gg.y : 0.f;
        float lz = (dd.z <= cutoff) ? gg.z : 0.f;
        float lw = (dd.w <= cutoff) ? gg.w : 0.f;
        p4[k] = make_float4(lx,ly,lz,lw);
        lmax = fmaxf(lmax, fmaxf(fmaxf(lx,ly), fmaxf(lz,lw)));
    }
    lmax = reduxMaxF(lmax);
    float Zs = 0.f;
    #pragma unroll
    for(int k=0;k<8;++k){
        float ex = __expf(p4[k].x - lmax);
        float ey = __expf(p4[k].y - lmax);
        float ez = __expf(p4[k].z - lmax);
        float ew = __expf(p4[k].w - lmax);
        p4[k] = make_float4(ex,ey,ez,ew);
        Zs += ex+ey+ez+ew;
    }
    Zs = warpRedSum(Zs);
    float inv = 1.0f / Zs;
    #pragma unroll
    for(int k=0;k<8;++k){
        float4 v = p4[k];
        v.x *= inv; v.y *= inv; v.z *= inv; v.w *= inv;
        slab[k*32 + lane] = v;
    }
    __syncthreads();
    float4* Srow = (float4*)(g_S + ((size_t)(b*N + i))*3*N);
    #pragma unroll 1
    for(int t4 = tid; t4 < 768; t4 += 288){
        int hh = t4 >> 8, j4 = t4 & 255;
        float4 a0 = ((const float4*)sAcc9[0*3+hh])[j4];
        float4 a1 = ((const float4*)sAcc9[1*3+hh])[j4];
        float4 a2 = ((const float4*)sAcc9[2*3+hh])[j4];
        Srow[t4] = make_float4(a0.x+a1.x+a2.x, a0.y+a1.y+a2.y,
                               a0.z+a1.z+a2.z, a0.w+a1.w+a2.w);
    }
}

// ---------- final: o[b][c][i] += sum_j S[b][i][hN+j] f[h][b][j][c] ----------
// grid (32, BATCH, 12): z = h*4 + sub; each block does 4 kk2 chunks (256 j's).
__global__ void k_final3(float* __restrict__ out){
    int b = blockIdx.y;
    int h = blockIdx.z >> 2, sub = blockIdx.z & 3;
    int i0 = blockIdx.x * 32;
    __shared__ float sST[64][40];   // [k][i], 160B row stride (16B-aligned)
    __shared__ float sF[64][65];
    int tid = threadIdx.x;
    int c = tid & 63, iq = tid >> 6;   // 8 i's per thread
    ull acc2[4] = {0ull, 0ull, 0ull, 0ull};
    #pragma unroll 1
    for(int kk2 = sub*4; kk2 < sub*4 + 4; ++kk2){
        {
            int r = tid >> 3, kb = (tid & 7)*8;
            const float* sp = g_S + ((size_t)(b*N + i0 + r))*3*N + h*N + kk2*64 + kb;
            float4 v0 = *(const float4*)sp;
            float4 v1 = *(const float4*)(sp+4);
            sST[kb+0][r] = v0.x; sST[kb+1][r] = v0.y;
            sST[kb+2][r] = v0.z; sST[kb+3][r] = v0.w;
            sST[kb+4][r] = v1.x; sST[kb+5][r] = v1.y;
            sST[kb+6][r] = v1.z; sST[kb+7][r] = v1.w;
        }
        {
            int j0 = kk2*64;
            const float* fp = g_f + ((size_t)(h*BATCH + b)*N + j0)*C;
            #pragma unroll
            for(int uu=0; uu<16; ++uu){
                int t = tid + uu*256;
                int r = t >> 6, cc = t & 63;
                sF[r][cc] = fp[r*C + cc];
            }
        }
        __syncthreads();
        #pragma unroll 8
        for(int k = 0; k < 64; ++k){
            ull fvd = pk2(sF[k][c]);
            float4 v0 = *(const float4*)&sST[k][iq*8];     // 32B-aligned (stride 160B)
            float4 v1 = *(const float4*)&sST[k][iq*8+4];
            ffma2(acc2[0], pk2f(v0.x, v0.y), fvd);
            ffma2(acc2[1], pk2f(v0.z, v0.w), fvd);
            ffma2(acc2[2], pk2f(v1.x, v1.y), fvd);
            ffma2(acc2[3], pk2f(v1.z, v1.w), fvd);
        }
        __syncthreads();
    }
    float2 a0 = up2(acc2[0]), a1 = up2(acc2[1]);
    float2 a2 = up2(acc2[2]), a3 = up2(acc2[3]);
    float* ob = out + (size_t)b*C*N + (size_t)c*N + i0 + iq*8;
    atomicAdd(ob+0, a0.x); atomicAdd(ob+1, a0.y);
    atomicAdd(ob+2, a1.x); atomicAdd(ob+3, a1.y);
    atomicAdd(ob+4, a2.x); atomicAdd(ob+5, a2.y);
    atomicAdd(ob+6, a3.x); atomicAdd(ob+7, a3.y);
}

extern "C" void kernel_launch(void* const* d_in, const int* in_sizes, int n_in,
                              void* d_out, int out_size){
    const float* x1 = (const float*)d_in[0];
    const float* x2 = (const float*)d_in[1];
    const float* x3 = (const float*)d_in[2];
    const float* w1 = (const float*)d_in[3];
    const float* b1 = (const float*)d_in[4];
    const float* w2 = (const float*)d_in[5];
    const float* b2 = (const float*)d_in[6];
    const float* w3 = (const float*)d_in[7];
    const float* b3 = (const float*)d_in[8];
    float* out = (float*)d_out;

    static int smem_set = 0;
    if(!smem_set){
        cudaFuncSetAttribute(k_gemm_all, cudaFuncAttributeMaxDynamicSharedMemorySize, 65536);
        smem_set = 1;
    }

    k_front<<<225, 256>>>(x1, x2, x3, w1, b1, w2, b2, w3, b3, out);
    k_gemm_all<<<dim3(64, 24), 256, 65536>>>();
    k_fa<<<dim3(N, BATCH), 288>>>();
    k_final3<<<dim3(32, BATCH, 12), 256>>>(out);
}